// round 4
// baseline (speedup 1.0000x reference)
#include <cuda_runtime.h>
#include <cstdint>

#define NMAX 50000
#define EMAX 1000000

// ---------------- scratch (static device globals; no allocation) ----------------
__device__ float g_rdeg[NMAX];
__device__ int   g_cnt[NMAX];
__device__ int   g_off[NMAX + 1];
__device__ int   g_cursor[NMAX];
__device__ int   g_bsum[64];
__device__ int   g_hist[128];
__device__ int   g_histcur[128];
__device__ int   g_perm[NMAX];
__device__ int2  g_erec[EMAX];                   // {src | rel<<17, w_bits}
__device__ float g_xt[(size_t)NMAX * 320];
__device__ float g_agg[(size_t)NMAX * 64];
__device__ float g_h[(size_t)NMAX * 64];

// ---------------- packed fp32x2 helpers ----------------
__device__ __forceinline__ void fma2(unsigned long long &a, unsigned long long x, unsigned long long w) {
    asm("fma.rn.f32x2 %0, %1, %2, %0;" : "+l"(a) : "l"(x), "l"(w));
}
__device__ __forceinline__ unsigned long long pack2(float v) {
    unsigned long long r;
    asm("mov.b64 %0, {%1, %1};" : "=l"(r) : "f"(v));
    return r;
}
__device__ __forceinline__ float2 unpack2(unsigned long long a) {
    float2 f;
    asm("mov.b64 {%0, %1}, %2;" : "=f"(f.x), "=f"(f.y) : "l"(a));
    return f;
}

// ---------------- degree / CSR build ----------------
extern "C" __global__ void k_deg(const int* __restrict__ ei, int* __restrict__ cnt, int E) {
    int e = blockIdx.x * blockDim.x + threadIdx.x;
    if (e < E) atomicAdd(&cnt[ei[E + e]], 1);
}
// exclusive scan over 1024-blocks; also emits rdeg and degree histogram
extern "C" __global__ void k_scan1(const int* __restrict__ cnt, int* __restrict__ off,
                                   float* __restrict__ rdeg, int* __restrict__ bsum,
                                   int* __restrict__ hist, int N) {
    __shared__ int wsum[32];
    int t = threadIdx.x, g = blockIdx.x * 1024 + t;
    int v = (g < N) ? cnt[g] : 0;
    int lane = t & 31, wid = t >> 5;
    int x = v;
    #pragma unroll
    for (int d = 1; d < 32; d <<= 1) {
        int y = __shfl_up_sync(0xFFFFFFFF, x, d);
        if (lane >= d) x += y;
    }
    if (lane == 31) wsum[wid] = x;
    __syncthreads();
    if (wid == 0) {
        int s = wsum[lane];
        #pragma unroll
        for (int d = 1; d < 32; d <<= 1) {
            int y = __shfl_up_sync(0xFFFFFFFF, s, d);
            if (lane >= d) s += y;
        }
        wsum[lane] = s;
    }
    __syncthreads();
    int incl = x + (wid > 0 ? wsum[wid - 1] : 0);
    if (g < N) {
        off[g] = incl - v;
        rdeg[g] = 1.0f / (float)max(v, 1);
        atomicAdd(&hist[min(v, 127)], 1);
    }
    if (t == 1023) bsum[blockIdx.x] = incl;
}
// both serial mini-scans in one launch: bsum (B entries) + hist (128 bins)
extern "C" __global__ void k_scan2h(int* __restrict__ bsum, int B,
                                    const int* __restrict__ hist, int* __restrict__ histcur) {
    if (threadIdx.x == 0) {
        int run = 0;
        for (int i = 0; i < B; i++) { int v = bsum[i]; bsum[i] = run; run += v; }
    } else if (threadIdx.x == 32) {
        int run = 0;
        for (int i = 0; i < 128; i++) { int v = hist[i]; histcur[i] = run; run += v; }
    }
}
extern "C" __global__ void k_scan3(int* __restrict__ off, int* __restrict__ cursor,
                                   const int* __restrict__ bsum, int N, int E) {
    int g = blockIdx.x * blockDim.x + threadIdx.x;
    if (g < N) {
        int o = off[g] + bsum[g >> 10];
        off[g] = o;
        cursor[g] = o;
    }
    if (g == 0) off[N] = E;
}
// counting-sort scatter: perm lists nodes ascending by degree
extern "C" __global__ void k_perm(const int* __restrict__ cnt, int* __restrict__ histcur,
                                  int* __restrict__ perm, int N) {
    int g = blockIdx.x * blockDim.x + threadIdx.x;
    if (g < N) {
        int d = min(cnt[g], 127);
        int pos = atomicAdd(&histcur[d], 1);
        perm[pos] = g;
    }
}
extern "C" __global__ void k_fill(const int* __restrict__ ei, const int* __restrict__ et,
                                  const float* __restrict__ ew, int* __restrict__ cursor,
                                  int2* __restrict__ erec, int E) {
    int e = blockIdx.x * blockDim.x + threadIdx.x;
    if (e >= E) return;
    int dst = ei[E + e];
    int pos = atomicAdd(&cursor[dst], 1);
    erec[pos] = make_int2(ei[e] | (et[e] << 17), __float_as_int(ew[e]));
}

// ---------------- transform: out[N,320] = A[N,64] @ [W0 | Wr0..Wr3] ----------------
#define XS_P 132
extern "C" __global__ void __launch_bounds__(256)
k_transform(const float* __restrict__ A, const float* __restrict__ W0,
            const float* __restrict__ Wr, float* __restrict__ out, int N) {
    extern __shared__ float sm[];
    float* xs = sm;              // [64][XS_P] k-major
    float* ws = sm + 64 * XS_P;  // [64][64]
    int t = threadIdx.x;
    int r0 = blockIdx.x * 128;

    for (int i = t; i < 128 * 64; i += 256) {
        int row = i >> 6, k = i & 63;
        int g = r0 + row;
        xs[k * XS_P + row] = (g < N) ? A[(size_t)g * 64 + k] : 0.f;
    }

    int tx = t & 7, ty = t >> 3;
    const float* xp = &xs[4 * ty];

    for (int pass = 0; pass < 5; pass++) {
        __syncthreads();
        for (int i = t; i < 64 * 64; i += 256)
            ws[i] = (pass == 0) ? W0[i] : Wr[(pass - 1) * 4096 + i];
        __syncthreads();

        unsigned long long acc[4][4];
        #pragma unroll
        for (int r = 0; r < 4; r++)
            #pragma unroll
            for (int j = 0; j < 4; j++) acc[r][j] = 0ULL;

        #pragma unroll 4
        for (int k = 0; k < 64; k++) {
            float4 xv = *(const float4*)&xp[k * XS_P];
            ulonglong2 wA = *(const ulonglong2*)&ws[k * 64 + 8 * tx];
            ulonglong2 wB = *(const ulonglong2*)&ws[k * 64 + 8 * tx + 4];
            unsigned long long x0 = pack2(xv.x), x1 = pack2(xv.y),
                               x2 = pack2(xv.z), x3 = pack2(xv.w);
            fma2(acc[0][0], x0, wA.x); fma2(acc[0][1], x0, wA.y);
            fma2(acc[0][2], x0, wB.x); fma2(acc[0][3], x0, wB.y);
            fma2(acc[1][0], x1, wA.x); fma2(acc[1][1], x1, wA.y);
            fma2(acc[1][2], x1, wB.x); fma2(acc[1][3], x1, wB.y);
            fma2(acc[2][0], x2, wA.x); fma2(acc[2][1], x2, wA.y);
            fma2(acc[2][2], x2, wB.x); fma2(acc[2][3], x2, wB.y);
            fma2(acc[3][0], x3, wA.x); fma2(acc[3][1], x3, wA.y);
            fma2(acc[3][2], x3, wB.x); fma2(acc[3][3], x3, wB.y);
        }
        #pragma unroll
        for (int r = 0; r < 4; r++) {
            int gr = r0 + 4 * ty + r;
            if (gr < N) {
                unsigned long long* op =
                    (unsigned long long*)&out[(size_t)gr * 320 + pass * 64 + 8 * tx];
                *(ulonglong2*)op       = make_ulonglong2(acc[r][0], acc[r][1]);
                *(ulonglong2*)(op + 2) = make_ulonglong2(acc[r][2], acc[r][3]);
            }
        }
    }
}

// ---------------- RGCN gather (degree-sorted, 4-way unrolled) + fused combine/relu ----------------
extern "C" __global__ void k_rgcn_gather(const int* __restrict__ perm, const int* __restrict__ off,
                                         const int2* __restrict__ erec,
                                         const float* __restrict__ xt, const float* __restrict__ rdeg,
                                         float* __restrict__ h, int N) {
    int idx = blockIdx.x * blockDim.x + threadIdx.x;
    int nid = idx >> 4;
    if (nid >= N) return;
    int node = __ldg(&perm[nid]);
    int lane = idx & 15;
    int beg = __ldg(&off[node]), end = __ldg(&off[node + 1]);
    const float4* xt4 = (const float4*)xt;   // row stride 80 float4s
    float4 a0 = {0,0,0,0}, a1 = {0,0,0,0}, a2 = {0,0,0,0}, a3 = {0,0,0,0};
    int i = beg;
    for (; i + 4 <= end; i += 4) {
        int2 r0 = __ldg(&erec[i]),     r1 = __ldg(&erec[i + 1]);
        int2 r2 = __ldg(&erec[i + 2]), r3 = __ldg(&erec[i + 3]);
        float4 v0 = __ldg(&xt4[(size_t)(r0.x & 0x1FFFF) * 80 + (((r0.x >> 17) + 1) << 4) + lane]);
        float4 v1 = __ldg(&xt4[(size_t)(r1.x & 0x1FFFF) * 80 + (((r1.x >> 17) + 1) << 4) + lane]);
        float4 v2 = __ldg(&xt4[(size_t)(r2.x & 0x1FFFF) * 80 + (((r2.x >> 17) + 1) << 4) + lane]);
        float4 v3 = __ldg(&xt4[(size_t)(r3.x & 0x1FFFF) * 80 + (((r3.x >> 17) + 1) << 4) + lane]);
        float w0 = __int_as_float(r0.y), w1 = __int_as_float(r1.y);
        float w2 = __int_as_float(r2.y), w3 = __int_as_float(r3.y);
        a0.x += w0*v0.x; a0.y += w0*v0.y; a0.z += w0*v0.z; a0.w += w0*v0.w;
        a1.x += w1*v1.x; a1.y += w1*v1.y; a1.z += w1*v1.z; a1.w += w1*v1.w;
        a2.x += w2*v2.x; a2.y += w2*v2.y; a2.z += w2*v2.z; a2.w += w2*v2.w;
        a3.x += w3*v3.x; a3.y += w3*v3.y; a3.z += w3*v3.z; a3.w += w3*v3.w;
    }
    for (; i < end; i++) {
        int2 r0 = __ldg(&erec[i]);
        float w0 = __int_as_float(r0.y);
        float4 v0 = __ldg(&xt4[(size_t)(r0.x & 0x1FFFF) * 80 + (((r0.x >> 17) + 1) << 4) + lane]);
        a0.x += w0*v0.x; a0.y += w0*v0.y; a0.z += w0*v0.z; a0.w += w0*v0.w;
    }
    float4 s = __ldg(&xt4[(size_t)node * 80 + lane]);
    float rd = __ldg(&rdeg[node]);
    float4 o;
    o.x = fmaxf((s.x + (a0.x + a1.x) + (a2.x + a3.x)) * rd, 0.f);
    o.y = fmaxf((s.y + (a0.y + a1.y) + (a2.y + a3.y)) * rd, 0.f);
    o.z = fmaxf((s.z + (a0.z + a1.z) + (a2.z + a3.z)) * rd, 0.f);
    o.w = fmaxf((s.w + (a0.w + a1.w) + (a2.w + a3.w)) * rd, 0.f);
    *(float4*)&h[((size_t)node << 6) + (lane << 2)] = o;
}

// ---------------- Group gather (degree-sorted): agg[n] = sum_e w_e * h[src_e] ----------------
extern "C" __global__ void k_group_gather(const int* __restrict__ perm, const int* __restrict__ off,
                                          const int2* __restrict__ erec,
                                          const float* __restrict__ h, float* __restrict__ agg, int N) {
    int idx = blockIdx.x * blockDim.x + threadIdx.x;
    int nid = idx >> 4;
    if (nid >= N) return;
    int node = __ldg(&perm[nid]);
    int lane = idx & 15;
    int beg = __ldg(&off[node]), end = __ldg(&off[node + 1]);
    const float4* h4 = (const float4*)h;     // row stride 16 float4s
    float4 a0 = {0,0,0,0}, a1 = {0,0,0,0}, a2 = {0,0,0,0}, a3 = {0,0,0,0};
    int i = beg;
    for (; i + 4 <= end; i += 4) {
        int2 r0 = __ldg(&erec[i]),     r1 = __ldg(&erec[i + 1]);
        int2 r2 = __ldg(&erec[i + 2]), r3 = __ldg(&erec[i + 3]);
        float4 v0 = __ldg(&h4[(size_t)((r0.x & 0x1FFFF) << 4) + lane]);
        float4 v1 = __ldg(&h4[(size_t)((r1.x & 0x1FFFF) << 4) + lane]);
        float4 v2 = __ldg(&h4[(size_t)((r2.x & 0x1FFFF) << 4) + lane]);
        float4 v3 = __ldg(&h4[(size_t)((r3.x & 0x1FFFF) << 4) + lane]);
        float w0 = __int_as_float(r0.y), w1 = __int_as_float(r1.y);
        float w2 = __int_as_float(r2.y), w3 = __int_as_float(r3.y);
        a0.x += w0*v0.x; a0.y += w0*v0.y; a0.z += w0*v0.z; a0.w += w0*v0.w;
        a1.x += w1*v1.x; a1.y += w1*v1.y; a1.z += w1*v1.z; a1.w += w1*v1.w;
        a2.x += w2*v2.x; a2.y += w2*v2.y; a2.z += w2*v2.z; a2.w += w2*v2.w;
        a3.x += w3*v3.x; a3.y += w3*v3.y; a3.z += w3*v3.z; a3.w += w3*v3.w;
    }
    for (; i < end; i++) {
        int2 r0 = __ldg(&erec[i]);
        float w0 = __int_as_float(r0.y);
        float4 v0 = __ldg(&h4[(size_t)((r0.x & 0x1FFFF) << 4) + lane]);
        a0.x += w0*v0.x; a0.y += w0*v0.y; a0.z += w0*v0.z; a0.w += w0*v0.w;
    }
    float4 o;
    o.x = (a0.x + a1.x) + (a2.x + a3.x);
    o.y = (a0.y + a1.y) + (a2.y + a3.y);
    o.z = (a0.z + a1.z) + (a2.z + a3.z);
    o.w = (a0.w + a1.w) + (a2.w + a3.w);
    *(float4*)&agg[((size_t)node << 6) + (lane << 2)] = o;
}

// ---------------- Group combine: h += alpha * ((agg*rdeg) @ W + b) ----------------
extern "C" __global__ void __launch_bounds__(256)
k_group_combine(const float* __restrict__ agg, const float* __restrict__ rdeg,
                const float* __restrict__ W, const float* __restrict__ b,
                const float* __restrict__ alpha_p, float* __restrict__ h, int N) {
    extern __shared__ float sm[];
    float* xs = sm;              // [64][XS_P]
    float* ws = sm + 64 * XS_P;  // [64][64]
    int t = threadIdx.x;
    int r0 = blockIdx.x * 128;

    for (int i = t; i < 128 * 64; i += 256) {
        int row = i >> 6, k = i & 63;
        int g = r0 + row;
        xs[k * XS_P + row] = (g < N) ? agg[(size_t)g * 64 + k] * rdeg[g] : 0.f;
    }
    for (int i = t; i < 64 * 64; i += 256) ws[i] = W[i];
    __syncthreads();

    float alpha = *alpha_p;
    int tx = t & 7, ty = t >> 3;
    const float* xp = &xs[4 * ty];

    unsigned long long acc[4][4];
    #pragma unroll
    for (int r = 0; r < 4; r++)
        #pragma unroll
        for (int j = 0; j < 4; j++) acc[r][j] = 0ULL;

    #pragma unroll 4
    for (int k = 0; k < 64; k++) {
        float4 xv = *(const float4*)&xp[k * XS_P];
        ulonglong2 wA = *(const ulonglong2*)&ws[k * 64 + 8 * tx];
        ulonglong2 wB = *(const ulonglong2*)&ws[k * 64 + 8 * tx + 4];
        unsigned long long x0 = pack2(xv.x), x1 = pack2(xv.y),
                           x2 = pack2(xv.z), x3 = pack2(xv.w);
        fma2(acc[0][0], x0, wA.x); fma2(acc[0][1], x0, wA.y);
        fma2(acc[0][2], x0, wB.x); fma2(acc[0][3], x0, wB.y);
        fma2(acc[1][0], x1, wA.x); fma2(acc[1][1], x1, wA.y);
        fma2(acc[1][2], x1, wB.x); fma2(acc[1][3], x1, wB.y);
        fma2(acc[2][0], x2, wA.x); fma2(acc[2][1], x2, wA.y);
        fma2(acc[2][2], x2, wB.x); fma2(acc[2][3], x2, wB.y);
        fma2(acc[3][0], x3, wA.x); fma2(acc[3][1], x3, wA.y);
        fma2(acc[3][2], x3, wB.x); fma2(acc[3][3], x3, wB.y);
    }
    float4 b0 = *(const float4*)&b[8 * tx];
    float4 b1 = *(const float4*)&b[8 * tx + 4];
    #pragma unroll
    for (int r = 0; r < 4; r++) {
        int gr = r0 + 4 * ty + r;
        if (gr < N) {
            float* hp = &h[((size_t)gr << 6) + 8 * tx];
            float4 h0 = *(float4*)hp;
            float4 h1 = *(float4*)(hp + 4);
            float2 f0 = unpack2(acc[r][0]), f1 = unpack2(acc[r][1]);
            float2 f2 = unpack2(acc[r][2]), f3 = unpack2(acc[r][3]);
            h0.x += alpha * (f0.x + b0.x); h0.y += alpha * (f0.y + b0.y);
            h0.z += alpha * (f1.x + b0.z); h0.w += alpha * (f1.y + b0.w);
            h1.x += alpha * (f2.x + b1.x); h1.y += alpha * (f2.y + b1.y);
            h1.z += alpha * (f3.x + b1.z); h1.w += alpha * (f3.y + b1.w);
            *(float4*)hp = h0;
            *(float4*)(hp + 4) = h1;
        }
    }
}

// ---------------- Output head: out = h @ outW[64,32] + outb ----------------
extern "C" __global__ void __launch_bounds__(256, 4)
k_head(const float* __restrict__ h, const float* __restrict__ W, const float* __restrict__ b,
       float* __restrict__ out, int N) {
    extern __shared__ float sm[];
    float* xs = sm;              // 128*65
    float* ws = sm + 128 * 65;   // 64*32
    int t = threadIdx.x;
    int r0 = blockIdx.x * 128;
    for (int i = t; i < 128 * 64; i += 256) {
        int rr = i >> 6, k = i & 63;
        int g = r0 + rr;
        xs[rr * 65 + k] = (g < N) ? h[(size_t)g * 64 + k] : 0.f;
    }
    for (int i = t; i < 64 * 32; i += 256) ws[i] = W[i];
    __syncthreads();
    int row = t & 127, th = t >> 7;
    int gr = r0 + row;
    const float* xrow = &xs[row * 65];
    for (int jt = 0; jt < 2; jt++) {
        int jl = (jt * 2 + th) * 8;
        unsigned long long a0 = 0, a1 = 0, a2 = 0, a3 = 0;
        #pragma unroll
        for (int k = 0; k < 64; k++) {
            unsigned long long xv = pack2(xrow[k]);
            const float* wp = &ws[k * 32 + jl];
            ulonglong2 wA = *(const ulonglong2*)wp;
            ulonglong2 wB = *(const ulonglong2*)(wp + 4);
            fma2(a0, xv, wA.x); fma2(a1, xv, wA.y);
            fma2(a2, xv, wB.x); fma2(a3, xv, wB.y);
        }
        if (gr < N) {
            float2 f0 = unpack2(a0), f1 = unpack2(a1), f2 = unpack2(a2), f3 = unpack2(a3);
            const float* bp = &b[jl];
            float* op = &out[(size_t)gr * 32 + jl];
            op[0] = f0.x + bp[0]; op[1] = f0.y + bp[1];
            op[2] = f1.x + bp[2]; op[3] = f1.y + bp[3];
            op[4] = f2.x + bp[4]; op[5] = f2.y + bp[5];
            op[6] = f3.x + bp[6]; op[7] = f3.y + bp[7];
        }
    }
}

// ---------------- launch ----------------
extern "C" void kernel_launch(void* const* d_in, const int* in_sizes, int n_in,
                              void* d_out, int out_size) {
    const float* x      = (const float*)d_in[0];
    const int*   ei     = (const int*)d_in[1];
    const int*   et     = (const int*)d_in[2];
    const float* ew     = (const float*)d_in[3];
    const float* W1     = (const float*)d_in[4];
    const float* W01    = (const float*)d_in[5];
    const float* alpha1 = (const float*)d_in[6];
    const float* projW1 = (const float*)d_in[7];
    const float* projb1 = (const float*)d_in[8];
    const float* W2     = (const float*)d_in[9];
    const float* W02    = (const float*)d_in[10];
    const float* alpha2 = (const float*)d_in[11];
    const float* projW2 = (const float*)d_in[12];
    const float* projb2 = (const float*)d_in[13];
    const float* outW   = (const float*)d_in[14];
    const float* outb   = (const float*)d_in[15];

    int N = in_sizes[0] / 64;
    int E = in_sizes[2];

    float *rdeg, *xt, *agg, *h;
    int *cnt, *off, *cursor, *bsum, *hist, *histcur, *perm;
    int2 *erec;
    cudaGetSymbolAddress((void**)&rdeg,    g_rdeg);
    cudaGetSymbolAddress((void**)&cnt,     g_cnt);
    cudaGetSymbolAddress((void**)&off,     g_off);
    cudaGetSymbolAddress((void**)&cursor,  g_cursor);
    cudaGetSymbolAddress((void**)&bsum,    g_bsum);
    cudaGetSymbolAddress((void**)&hist,    g_hist);
    cudaGetSymbolAddress((void**)&histcur, g_histcur);
    cudaGetSymbolAddress((void**)&perm,    g_perm);
    cudaGetSymbolAddress((void**)&erec,    g_erec);
    cudaGetSymbolAddress((void**)&xt,      g_xt);
    cudaGetSymbolAddress((void**)&agg,     g_agg);
    cudaGetSymbolAddress((void**)&h,       g_h);

    static cudaStream_t s2 = nullptr;
    static cudaEvent_t evFork = nullptr, evJoin = nullptr;
    if (s2 == nullptr) {
        cudaStreamCreateWithFlags(&s2, cudaStreamNonBlocking);
        cudaEventCreateWithFlags(&evFork, cudaEventDisableTiming);
        cudaEventCreateWithFlags(&evJoin, cudaEventDisableTiming);
    }

    const int SMEM_T = (64 * XS_P + 64 * 64) * 4;
    const int SMEM_H = (128 * 65 + 64 * 32) * 4;
    cudaFuncSetAttribute(k_transform,     cudaFuncAttributeMaxDynamicSharedMemorySize, SMEM_T);
    cudaFuncSetAttribute(k_group_combine, cudaFuncAttributeMaxDynamicSharedMemorySize, SMEM_T);
    cudaFuncSetAttribute(k_head,          cudaFuncAttributeMaxDynamicSharedMemorySize, SMEM_H);

    int ebl  = (E + 255) / 256;
    int nbl  = (N + 255) / 256;
    int gthr = (N * 16 + 255) / 256;
    int gbl  = (N + 127) / 128;
    int B1   = (N + 1023) / 1024;

    // ---- fork: CSR build + degree sort on s2, transform layer 1 on main ----
    cudaEventRecord(evFork, 0);
    cudaStreamWaitEvent(s2, evFork, 0);

    cudaMemsetAsync(cnt, 0, (size_t)N * sizeof(int), s2);
    cudaMemsetAsync(hist, 0, 128 * sizeof(int), s2);
    k_deg<<<ebl, 256, 0, s2>>>(ei, cnt, E);
    k_scan1<<<B1, 1024, 0, s2>>>(cnt, off, rdeg, bsum, hist, N);
    k_scan2h<<<1, 64, 0, s2>>>(bsum, B1, hist, histcur);
    k_scan3<<<nbl, 256, 0, s2>>>(off, cursor, bsum, N, E);
    k_perm<<<nbl, 256, 0, s2>>>(cnt, histcur, perm, N);
    k_fill<<<ebl, 256, 0, s2>>>(ei, et, ew, cursor, erec, E);
    cudaEventRecord(evJoin, s2);

    k_transform<<<gbl, 256, SMEM_T>>>(x, W01, W1, xt, N);

    cudaStreamWaitEvent(0, evJoin, 0);

    // ---- layer 1 ----
    k_rgcn_gather<<<gthr, 256>>>(perm, off, erec, xt, rdeg, h, N);
    k_group_gather<<<gthr, 256>>>(perm, off, erec, h, agg, N);
    k_group_combine<<<gbl, 256, SMEM_T>>>(agg, rdeg, projW1, projb1, alpha1, h, N);

    // ---- layer 2 ----
    k_transform<<<gbl, 256, SMEM_T>>>(h, W02, W2, xt, N);
    k_rgcn_gather<<<gthr, 256>>>(perm, off, erec, xt, rdeg, h, N);
    k_group_gather<<<gthr, 256>>>(perm, off, erec, h, agg, N);
    k_group_combine<<<gbl, 256, SMEM_T>>>(agg, rdeg, projW2, projb2, alpha2, h, N);

    // ---- head ----
    k_head<<<gbl, 256, SMEM_H>>>(h, outW, outb, (float*)d_out, N);
}

// round 5
// speedup vs baseline: 1.0294x; 1.0294x over previous
#include <cuda_runtime.h>
#include <cuda_fp16.h>
#include <cstdint>

#define NMAX 50000
#define EMAX 1000000
#define XS_P 132

// ---------------- scratch (static device globals; no allocation) ----------------
__device__ int    g_cntflag[NMAX + 64];           // [0,NMAX): deg counts, [NMAX,NMAX+64): scan flags
__device__ int    g_pref[64];                     // scan block inclusive prefixes (flag-guarded)
__device__ int    g_off[NMAX + 1];
__device__ int    g_cursor[NMAX];
__device__ float  g_rdeg[NMAX];
__device__ int2   g_erec[EMAX];                   // {src | rel<<17, w_bits}
__device__ __half g_xt[(size_t)NMAX * 320];       // fp16 transformed feats [W0 | Wr0..Wr3]
__device__ __half g_h[(size_t)NMAX * 64];         // fp16 hidden state
__device__ float  g_agg[(size_t)NMAX * 64];       // fp32 group aggregation

// ---------------- packed fp32x2 helpers ----------------
__device__ __forceinline__ void fma2(unsigned long long &a, unsigned long long x, unsigned long long w) {
    asm("fma.rn.f32x2 %0, %1, %2, %0;" : "+l"(a) : "l"(x), "l"(w));
}
__device__ __forceinline__ unsigned long long pack2(float v) {
    unsigned long long r;
    asm("mov.b64 %0, {%1, %1};" : "=l"(r) : "f"(v));
    return r;
}
__device__ __forceinline__ float2 unpack2(unsigned long long a) {
    float2 f;
    asm("mov.b64 {%0, %1}, %2;" : "=f"(f.x), "=f"(f.y) : "l"(a));
    return f;
}
__device__ __forceinline__ unsigned h2u(__half2 h) { return *(unsigned*)&h; }

// ---------------- degree ----------------
extern "C" __global__ void k_deg(const int* __restrict__ ei, int* __restrict__ cnt, int E) {
    int e = blockIdx.x * blockDim.x + threadIdx.x;
    if (e < E) atomicAdd(&cnt[ei[E + e]], 1);
}

// ---------------- single-pass chained scan: off/cursor/rdeg in one kernel ----------------
extern "C" __global__ void __launch_bounds__(1024)
k_scanAll(const int* __restrict__ cnt, int* __restrict__ flag, int* __restrict__ pref,
          int* __restrict__ off, int* __restrict__ cursor, float* __restrict__ rdeg,
          int N, int E) {
    __shared__ int wsum[32];
    __shared__ int s_pref;
    int t = threadIdx.x, b = blockIdx.x, g = b * 1024 + t;
    int v = (g < N) ? cnt[g] : 0;
    int lane = t & 31, wid = t >> 5;
    int x = v;
    #pragma unroll
    for (int d = 1; d < 32; d <<= 1) {
        int y = __shfl_up_sync(0xFFFFFFFF, x, d);
        if (lane >= d) x += y;
    }
    if (lane == 31) wsum[wid] = x;
    __syncthreads();
    if (wid == 0) {
        int s = wsum[lane];
        #pragma unroll
        for (int d = 1; d < 32; d <<= 1) {
            int y = __shfl_up_sync(0xFFFFFFFF, s, d);
            if (lane >= d) s += y;
        }
        wsum[lane] = s;
    }
    __syncthreads();
    int incl = x + (wid > 0 ? wsum[wid - 1] : 0);
    // chained lookback (49 blocks, all resident)
    if (t == 0) {
        int p = 0;
        if (b > 0) {
            while (atomicAdd(&flag[b - 1], 0) == 0) __nanosleep(40);
            __threadfence();
            p = pref[b - 1];
        }
        s_pref = p;
        pref[b] = p + wsum[31];
        __threadfence();
        atomicExch(&flag[b], 1);
    }
    __syncthreads();
    int base = s_pref;
    if (g < N) {
        int o = base + incl - v;
        off[g] = o;
        cursor[g] = o;
        rdeg[g] = 1.0f / (float)max(v, 1);
    }
    if (g == 0) off[N] = E;
}

extern "C" __global__ void k_fill(const int* __restrict__ ei, const int* __restrict__ et,
                                  const float* __restrict__ ew, int* __restrict__ cursor,
                                  int2* __restrict__ erec, int E) {
    int e = blockIdx.x * blockDim.x + threadIdx.x;
    if (e >= E) return;
    int dst = ei[E + e];
    int pos = atomicAdd(&cursor[dst], 1);
    erec[pos] = make_int2(ei[e] | (et[e] << 17), __float_as_int(ew[e]));
}

// ---------------- transform: out_h[N,320] = A[N,64] @ [W0 | Wr0..Wr3], fp16 output ----------------
template <bool HALF_IN>
__device__ __forceinline__ void transform_impl(const void* Ain, const float* __restrict__ W0,
                                               const float* __restrict__ Wr,
                                               __half* __restrict__ out, int N) {
    extern __shared__ float sm[];
    float* xs = sm;              // [64][XS_P] k-major
    float* ws = sm + 64 * XS_P;  // [64][64]
    int t = threadIdx.x;
    int r0 = blockIdx.x * 128;

    if (HALF_IN) {
        const __half* A = (const __half*)Ain;
        for (int i = t; i < 128 * 32; i += 256) {
            int row = i >> 5, kk = (i & 31) * 2;
            int g = r0 + row;
            float2 f = {0.f, 0.f};
            if (g < N) f = __half22float2(*(const __half2*)&A[(size_t)g * 64 + kk]);
            xs[kk * XS_P + row] = f.x;
            xs[(kk + 1) * XS_P + row] = f.y;
        }
    } else {
        const float* A = (const float*)Ain;
        for (int i = t; i < 128 * 64; i += 256) {
            int row = i >> 6, k = i & 63;
            int g = r0 + row;
            xs[k * XS_P + row] = (g < N) ? A[(size_t)g * 64 + k] : 0.f;
        }
    }

    int tx = t & 7, ty = t >> 3;
    const float* xp = &xs[4 * ty];

    for (int pass = 0; pass < 5; pass++) {
        __syncthreads();
        for (int i = t; i < 64 * 64; i += 256)
            ws[i] = (pass == 0) ? W0[i] : Wr[(pass - 1) * 4096 + i];
        __syncthreads();

        unsigned long long acc[4][4];
        #pragma unroll
        for (int r = 0; r < 4; r++)
            #pragma unroll
            for (int j = 0; j < 4; j++) acc[r][j] = 0ULL;

        #pragma unroll 4
        for (int k = 0; k < 64; k++) {
            float4 xv = *(const float4*)&xp[k * XS_P];
            ulonglong2 wA = *(const ulonglong2*)&ws[k * 64 + 8 * tx];
            ulonglong2 wB = *(const ulonglong2*)&ws[k * 64 + 8 * tx + 4];
            unsigned long long x0 = pack2(xv.x), x1 = pack2(xv.y),
                               x2 = pack2(xv.z), x3 = pack2(xv.w);
            fma2(acc[0][0], x0, wA.x); fma2(acc[0][1], x0, wA.y);
            fma2(acc[0][2], x0, wB.x); fma2(acc[0][3], x0, wB.y);
            fma2(acc[1][0], x1, wA.x); fma2(acc[1][1], x1, wA.y);
            fma2(acc[1][2], x1, wB.x); fma2(acc[1][3], x1, wB.y);
            fma2(acc[2][0], x2, wA.x); fma2(acc[2][1], x2, wA.y);
            fma2(acc[2][2], x2, wB.x); fma2(acc[2][3], x2, wB.y);
            fma2(acc[3][0], x3, wA.x); fma2(acc[3][1], x3, wA.y);
            fma2(acc[3][2], x3, wB.x); fma2(acc[3][3], x3, wB.y);
        }
        #pragma unroll
        for (int r = 0; r < 4; r++) {
            int gr = r0 + 4 * ty + r;
            if (gr < N) {
                float2 f0 = unpack2(acc[r][0]), f1 = unpack2(acc[r][1]);
                float2 f2 = unpack2(acc[r][2]), f3 = unpack2(acc[r][3]);
                uint4 ov;
                ov.x = h2u(__floats2half2_rn(f0.x, f0.y));
                ov.y = h2u(__floats2half2_rn(f1.x, f1.y));
                ov.z = h2u(__floats2half2_rn(f2.x, f2.y));
                ov.w = h2u(__floats2half2_rn(f3.x, f3.y));
                *(uint4*)&out[(size_t)gr * 320 + pass * 64 + 8 * tx] = ov;
            }
        }
    }
}
extern "C" __global__ void __launch_bounds__(256)
k_transform_f32(const float* A, const float* W0, const float* Wr, __half* out, int N) {
    transform_impl<false>(A, W0, Wr, out, N);
}
extern "C" __global__ void __launch_bounds__(256)
k_transform_f16(const __half* A, const float* W0, const float* Wr, __half* out, int N) {
    transform_impl<true>(A, W0, Wr, out, N);
}

// ---------------- RGCN gather (fp16 feats, 16 lanes x 4 halves) + fused combine/relu ----------------
extern "C" __global__ void k_rgcn_gather(const int* __restrict__ off, const int2* __restrict__ erec,
                                         const __half* __restrict__ xt, const float* __restrict__ rdeg,
                                         __half* __restrict__ h, int N) {
    int idx = blockIdx.x * blockDim.x + threadIdx.x;
    int node = idx >> 4;
    if (node >= N) return;
    int lane = idx & 15;
    int beg = __ldg(&off[node]), end = __ldg(&off[node + 1]);
    const uint2* xtp = (const uint2*)xt;   // row stride 80 uint2 (320 halves)
    float2 l0 = {0,0}, u0 = {0,0}, l1 = {0,0}, u1 = {0,0};
    float2 l2 = {0,0}, u2 = {0,0}, l3 = {0,0}, u3 = {0,0};
    int i = beg;
    for (; i + 4 <= end; i += 4) {
        int2 r0 = __ldg(&erec[i]),     r1 = __ldg(&erec[i + 1]);
        int2 r2 = __ldg(&erec[i + 2]), r3 = __ldg(&erec[i + 3]);
        uint2 v0 = __ldg(&xtp[(size_t)(r0.x & 0x1FFFF) * 80 + (((r0.x >> 17) + 1) << 4) + lane]);
        uint2 v1 = __ldg(&xtp[(size_t)(r1.x & 0x1FFFF) * 80 + (((r1.x >> 17) + 1) << 4) + lane]);
        uint2 v2 = __ldg(&xtp[(size_t)(r2.x & 0x1FFFF) * 80 + (((r2.x >> 17) + 1) << 4) + lane]);
        uint2 v3 = __ldg(&xtp[(size_t)(r3.x & 0x1FFFF) * 80 + (((r3.x >> 17) + 1) << 4) + lane]);
        float w0 = __int_as_float(r0.y), w1 = __int_as_float(r1.y);
        float w2 = __int_as_float(r2.y), w3 = __int_as_float(r3.y);
        float2 f;
        f = __half22float2(*(__half2*)&v0.x); l0.x += w0*f.x; l0.y += w0*f.y;
        f = __half22float2(*(__half2*)&v0.y); u0.x += w0*f.x; u0.y += w0*f.y;
        f = __half22float2(*(__half2*)&v1.x); l1.x += w1*f.x; l1.y += w1*f.y;
        f = __half22float2(*(__half2*)&v1.y); u1.x += w1*f.x; u1.y += w1*f.y;
        f = __half22float2(*(__half2*)&v2.x); l2.x += w2*f.x; l2.y += w2*f.y;
        f = __half22float2(*(__half2*)&v2.y); u2.x += w2*f.x; u2.y += w2*f.y;
        f = __half22float2(*(__half2*)&v3.x); l3.x += w3*f.x; l3.y += w3*f.y;
        f = __half22float2(*(__half2*)&v3.y); u3.x += w3*f.x; u3.y += w3*f.y;
    }
    for (; i < end; i++) {
        int2 r0 = __ldg(&erec[i]);
        float w0 = __int_as_float(r0.y);
        uint2 v0 = __ldg(&xtp[(size_t)(r0.x & 0x1FFFF) * 80 + (((r0.x >> 17) + 1) << 4) + lane]);
        float2 f;
        f = __half22float2(*(__half2*)&v0.x); l0.x += w0*f.x; l0.y += w0*f.y;
        f = __half22float2(*(__half2*)&v0.y); u0.x += w0*f.x; u0.y += w0*f.y;
    }
    float2 L = { (l0.x + l1.x) + (l2.x + l3.x), (l0.y + l1.y) + (l2.y + l3.y) };
    float2 U = { (u0.x + u1.x) + (u2.x + u3.x), (u0.y + u1.y) + (u2.y + u3.y) };
    uint2 sv = __ldg(&xtp[(size_t)node * 80 + lane]);
    float2 s0 = __half22float2(*(__half2*)&sv.x);
    float2 s1 = __half22float2(*(__half2*)&sv.y);
    float rd = __ldg(&rdeg[node]);
    float o0 = fmaxf((s0.x + L.x) * rd, 0.f);
    float o1 = fmaxf((s0.y + L.y) * rd, 0.f);
    float o2 = fmaxf((s1.x + U.x) * rd, 0.f);
    float o3 = fmaxf((s1.y + U.y) * rd, 0.f);
    uint2 ov;
    ov.x = h2u(__floats2half2_rn(o0, o1));
    ov.y = h2u(__floats2half2_rn(o2, o3));
    *(uint2*)&h[((size_t)node << 6) + (lane << 2)] = ov;
}

// ---------------- Group gather: agg[n] = sum_e w_e * h[src_e]  (fp16 in, fp32 out) ----------------
extern "C" __global__ void k_group_gather(const int* __restrict__ off, const int2* __restrict__ erec,
                                          const __half* __restrict__ h, float* __restrict__ agg, int N) {
    int idx = blockIdx.x * blockDim.x + threadIdx.x;
    int node = idx >> 4;
    if (node >= N) return;
    int lane = idx & 15;
    int beg = __ldg(&off[node]), end = __ldg(&off[node + 1]);
    const uint2* hp = (const uint2*)h;     // row stride 16 uint2 (64 halves)
    float2 l0 = {0,0}, u0 = {0,0}, l1 = {0,0}, u1 = {0,0};
    float2 l2 = {0,0}, u2 = {0,0}, l3 = {0,0}, u3 = {0,0};
    int i = beg;
    for (; i + 4 <= end; i += 4) {
        int2 r0 = __ldg(&erec[i]),     r1 = __ldg(&erec[i + 1]);
        int2 r2 = __ldg(&erec[i + 2]), r3 = __ldg(&erec[i + 3]);
        uint2 v0 = __ldg(&hp[(size_t)((r0.x & 0x1FFFF) << 4) + lane]);
        uint2 v1 = __ldg(&hp[(size_t)((r1.x & 0x1FFFF) << 4) + lane]);
        uint2 v2 = __ldg(&hp[(size_t)((r2.x & 0x1FFFF) << 4) + lane]);
        uint2 v3 = __ldg(&hp[(size_t)((r3.x & 0x1FFFF) << 4) + lane]);
        float w0 = __int_as_float(r0.y), w1 = __int_as_float(r1.y);
        float w2 = __int_as_float(r2.y), w3 = __int_as_float(r3.y);
        float2 f;
        f = __half22float2(*(__half2*)&v0.x); l0.x += w0*f.x; l0.y += w0*f.y;
        f = __half22float2(*(__half2*)&v0.y); u0.x += w0*f.x; u0.y += w0*f.y;
        f = __half22float2(*(__half2*)&v1.x); l1.x += w1*f.x; l1.y += w1*f.y;
        f = __half22float2(*(__half2*)&v1.y); u1.x += w1*f.x; u1.y += w1*f.y;
        f = __half22float2(*(__half2*)&v2.x); l2.x += w2*f.x; l2.y += w2*f.y;
        f = __half22float2(*(__half2*)&v2.y); u2.x += w2*f.x; u2.y += w2*f.y;
        f = __half22float2(*(__half2*)&v3.x); l3.x += w3*f.x; l3.y += w3*f.y;
        f = __half22float2(*(__half2*)&v3.y); u3.x += w3*f.x; u3.y += w3*f.y;
    }
    for (; i < end; i++) {
        int2 r0 = __ldg(&erec[i]);
        float w0 = __int_as_float(r0.y);
        uint2 v0 = __ldg(&hp[(size_t)((r0.x & 0x1FFFF) << 4) + lane]);
        float2 f;
        f = __half22float2(*(__half2*)&v0.x); l0.x += w0*f.x; l0.y += w0*f.y;
        f = __half22float2(*(__half2*)&v0.y); u0.x += w0*f.x; u0.y += w0*f.y;
    }
    float4 o;
    o.x = (l0.x + l1.x) + (l2.x + l3.x);
    o.y = (l0.y + l1.y) + (l2.y + l3.y);
    o.z = (u0.x + u1.x) + (u2.x + u3.x);
    o.w = (u0.y + u1.y) + (u2.y + u3.y);
    *(float4*)&agg[((size_t)node << 6) + (lane << 2)] = o;
}

// ---------------- Group combine: h += alpha * ((agg*rdeg) @ W + b), fp16 h ----------------
extern "C" __global__ void __launch_bounds__(256)
k_group_combine(const float* __restrict__ agg, const float* __restrict__ rdeg,
                const float* __restrict__ W, const float* __restrict__ b,
                const float* __restrict__ alpha_p, __half* __restrict__ h, int N) {
    extern __shared__ float sm[];
    float* xs = sm;              // [64][XS_P]
    float* ws = sm + 64 * XS_P;  // [64][64]
    int t = threadIdx.x;
    int r0 = blockIdx.x * 128;

    for (int i = t; i < 128 * 64; i += 256) {
        int row = i >> 6, k = i & 63;
        int g = r0 + row;
        xs[k * XS_P + row] = (g < N) ? agg[(size_t)g * 64 + k] * rdeg[g] : 0.f;
    }
    for (int i = t; i < 64 * 64; i += 256) ws[i] = W[i];
    __syncthreads();

    float alpha = *alpha_p;
    int tx = t & 7, ty = t >> 3;
    const float* xp = &xs[4 * ty];

    unsigned long long acc[4][4];
    #pragma unroll
    for (int r = 0; r < 4; r++)
        #pragma unroll
        for (int j = 0; j < 4; j++) acc[r][j] = 0ULL;

    #pragma unroll 4
    for (int k = 0; k < 64; k++) {
        float4 xv = *(const float4*)&xp[k * XS_P];
        ulonglong2 wA = *(const ulonglong2*)&ws[k * 64 + 8 * tx];
        ulonglong2 wB = *(const ulonglong2*)&ws[k * 64 + 8 * tx + 4];
        unsigned long long x0 = pack2(xv.x), x1 = pack2(xv.y),
                           x2 = pack2(xv.z), x3 = pack2(xv.w);
        fma2(acc[0][0], x0, wA.x); fma2(acc[0][1], x0, wA.y);
        fma2(acc[0][2], x0, wB.x); fma2(acc[0][3], x0, wB.y);
        fma2(acc[1][0], x1, wA.x); fma2(acc[1][1], x1, wA.y);
        fma2(acc[1][2], x1, wB.x); fma2(acc[1][3], x1, wB.y);
        fma2(acc[2][0], x2, wA.x); fma2(acc[2][1], x2, wA.y);
        fma2(acc[2][2], x2, wB.x); fma2(acc[2][3], x2, wB.y);
        fma2(acc[3][0], x3, wA.x); fma2(acc[3][1], x3, wA.y);
        fma2(acc[3][2], x3, wB.x); fma2(acc[3][3], x3, wB.y);
    }
    float4 b0 = *(const float4*)&b[8 * tx];
    float4 b1 = *(const float4*)&b[8 * tx + 4];
    #pragma unroll
    for (int r = 0; r < 4; r++) {
        int gr = r0 + 4 * ty + r;
        if (gr < N) {
            __half* hpp = &h[((size_t)gr << 6) + 8 * tx];
            uint4 hv = *(uint4*)hpp;
            float2 g0 = __half22float2(*(__half2*)&hv.x);
            float2 g1 = __half22float2(*(__half2*)&hv.y);
            float2 g2 = __half22float2(*(__half2*)&hv.z);
            float2 g3 = __half22float2(*(__half2*)&hv.w);
            float2 f0 = unpack2(acc[r][0]), f1 = unpack2(acc[r][1]);
            float2 f2 = unpack2(acc[r][2]), f3 = unpack2(acc[r][3]);
            g0.x += alpha * (f0.x + b0.x); g0.y += alpha * (f0.y + b0.y);
            g1.x += alpha * (f1.x + b0.z); g1.y += alpha * (f1.y + b0.w);
            g2.x += alpha * (f2.x + b1.x); g2.y += alpha * (f2.y + b1.y);
            g3.x += alpha * (f3.x + b1.z); g3.y += alpha * (f3.y + b1.w);
            uint4 ov;
            ov.x = h2u(__floats2half2_rn(g0.x, g0.y));
            ov.y = h2u(__floats2half2_rn(g1.x, g1.y));
            ov.z = h2u(__floats2half2_rn(g2.x, g2.y));
            ov.w = h2u(__floats2half2_rn(g3.x, g3.y));
            *(uint4*)hpp = ov;
        }
    }
}

// ---------------- Output head: out = h @ outW[64,32] + outb (fp16 in, fp32 out) ----------------
extern "C" __global__ void __launch_bounds__(256, 4)
k_head(const __half* __restrict__ h, const float* __restrict__ W, const float* __restrict__ b,
       float* __restrict__ out, int N) {
    extern __shared__ float sm[];
    float* xs = sm;              // 128*65
    float* ws = sm + 128 * 65;   // 64*32
    int t = threadIdx.x;
    int r0 = blockIdx.x * 128;
    for (int i = t; i < 128 * 32; i += 256) {
        int rr = i >> 5, kk = (i & 31) * 2;
        int g = r0 + rr;
        float2 f = {0.f, 0.f};
        if (g < N) f = __half22float2(*(const __half2*)&h[(size_t)g * 64 + kk]);
        xs[rr * 65 + kk] = f.x;
        xs[rr * 65 + kk + 1] = f.y;
    }
    for (int i = t; i < 64 * 32; i += 256) ws[i] = W[i];
    __syncthreads();
    int row = t & 127, th = t >> 7;
    int gr = r0 + row;
    const float* xrow = &xs[row * 65];
    for (int jt = 0; jt < 2; jt++) {
        int jl = (jt * 2 + th) * 8;
        unsigned long long a0 = 0, a1 = 0, a2 = 0, a3 = 0;
        #pragma unroll
        for (int k = 0; k < 64; k++) {
            unsigned long long xv = pack2(xrow[k]);
            const float* wp = &ws[k * 32 + jl];
            ulonglong2 wA = *(const ulonglong2*)wp;
            ulonglong2 wB = *(const ulonglong2*)(wp + 4);
            fma2(a0, xv, wA.x); fma2(a1, xv, wA.y);
            fma2(a2, xv, wB.x); fma2(a3, xv, wB.y);
        }
        if (gr < N) {
            float2 f0 = unpack2(a0), f1 = unpack2(a1), f2 = unpack2(a2), f3 = unpack2(a3);
            const float* bp = &b[jl];
            float* op = &out[(size_t)gr * 32 + jl];
            op[0] = f0.x + bp[0]; op[1] = f0.y + bp[1];
            op[2] = f1.x + bp[2]; op[3] = f1.y + bp[3];
            op[4] = f2.x + bp[4]; op[5] = f2.y + bp[5];
            op[6] = f3.x + bp[6]; op[7] = f3.y + bp[7];
        }
    }
}

// ---------------- launch ----------------
extern "C" void kernel_launch(void* const* d_in, const int* in_sizes, int n_in,
                              void* d_out, int out_size) {
    const float* x      = (const float*)d_in[0];
    const int*   ei     = (const int*)d_in[1];
    const int*   et     = (const int*)d_in[2];
    const float* ew     = (const float*)d_in[3];
    const float* W1     = (const float*)d_in[4];
    const float* W01    = (const float*)d_in[5];
    const float* alpha1 = (const float*)d_in[6];
    const float* projW1 = (const float*)d_in[7];
    const float* projb1 = (const float*)d_in[8];
    const float* W2     = (const float*)d_in[9];
    const float* W02    = (const float*)d_in[10];
    const float* alpha2 = (const float*)d_in[11];
    const float* projW2 = (const float*)d_in[12];
    const float* projb2 = (const float*)d_in[13];
    const float* outW   = (const float*)d_in[14];
    const float* outb   = (const float*)d_in[15];

    int N = in_sizes[0] / 64;
    int E = in_sizes[2];

    float *rdeg, *agg;
    int *cntflag, *pref, *off, *cursor;
    int2 *erec;
    __half *xt, *h;
    cudaGetSymbolAddress((void**)&cntflag, g_cntflag);
    cudaGetSymbolAddress((void**)&pref,    g_pref);
    cudaGetSymbolAddress((void**)&off,     g_off);
    cudaGetSymbolAddress((void**)&cursor,  g_cursor);
    cudaGetSymbolAddress((void**)&rdeg,    g_rdeg);
    cudaGetSymbolAddress((void**)&erec,    g_erec);
    cudaGetSymbolAddress((void**)&xt,      g_xt);
    cudaGetSymbolAddress((void**)&h,       g_h);
    cudaGetSymbolAddress((void**)&agg,     g_agg);

    static cudaStream_t s2 = nullptr;
    static cudaEvent_t evFork = nullptr, evJoin = nullptr;
    if (s2 == nullptr) {
        cudaStreamCreateWithFlags(&s2, cudaStreamNonBlocking);
        cudaEventCreateWithFlags(&evFork, cudaEventDisableTiming);
        cudaEventCreateWithFlags(&evJoin, cudaEventDisableTiming);
    }

    const int SMEM_T = (64 * XS_P + 64 * 64) * 4;
    const int SMEM_H = (128 * 65 + 64 * 32) * 4;
    cudaFuncSetAttribute(k_transform_f32,  cudaFuncAttributeMaxDynamicSharedMemorySize, SMEM_T);
    cudaFuncSetAttribute(k_transform_f16,  cudaFuncAttributeMaxDynamicSharedMemorySize, SMEM_T);
    cudaFuncSetAttribute(k_group_combine,  cudaFuncAttributeMaxDynamicSharedMemorySize, SMEM_T);
    cudaFuncSetAttribute(k_head,           cudaFuncAttributeMaxDynamicSharedMemorySize, SMEM_H);

    int ebl  = (E + 255) / 256;
    int gthr = (N * 16 + 255) / 256;
    int gbl  = (N + 127) / 128;
    int B1   = (N + 1023) / 1024;

    // ---- fork: transform L1 on main (launch #1), CSR build on s2 ----
    cudaEventRecord(evFork, 0);
    cudaStreamWaitEvent(s2, evFork, 0);

    k_transform_f32<<<gbl, 256, SMEM_T>>>(x, W01, W1, xt, N);          // #1

    cudaMemsetAsync(cntflag, 0, (size_t)(NMAX + 64) * sizeof(int), s2); // #2
    k_deg<<<ebl, 256, 0, s2>>>(ei, cntflag, E);                         // #3
    k_scanAll<<<B1, 1024, 0, s2>>>(cntflag, cntflag + NMAX, pref,
                                   off, cursor, rdeg, N, E);            // #4
    k_fill<<<ebl, 256, 0, s2>>>(ei, et, ew, cursor, erec, E);           // #5
    cudaEventRecord(evJoin, s2);

    cudaStreamWaitEvent(0, evJoin, 0);

    // ---- layer 1 ----
    k_rgcn_gather<<<gthr, 256>>>(off, erec, xt, rdeg, h, N);            // #6  <- ncu capture
    k_group_gather<<<gthr, 256>>>(off, erec, h, agg, N);
    k_group_combine<<<gbl, 256, SMEM_T>>>(agg, rdeg, projW1, projb1, alpha1, h, N);

    // ---- layer 2 ----
    k_transform_f16<<<gbl, 256, SMEM_T>>>(h, W02, W2, xt, N);
    k_rgcn_gather<<<gthr, 256>>>(off, erec, xt, rdeg, h, N);
    k_group_gather<<<gthr, 256>>>(off, erec, h, agg, N);
    k_group_combine<<<gbl, 256, SMEM_T>>>(agg, rdeg, projW2, projb2, alpha2, h, N);

    // ---- head ----
    k_head<<<gbl, 256, SMEM_H>>>(h, outW, outb, (float*)d_out, N);
}

// round 6
// speedup vs baseline: 1.1807x; 1.1470x over previous
#include <cuda_runtime.h>
#include <cstdint>

#define NMAX 50000
#define EMAX 1000000
#define XS_P 132
#define TXP 68     // A-tile smem pitch (tf32 words)
#define TWP 72     // W-tile smem pitch (tf32 words)

// ---------------- scratch (static device globals; no allocation) ----------------
__device__ int   g_cntflag[NMAX + 64];           // [0,NMAX): deg counts, then scan flags
__device__ int   g_pref[64];
__device__ int   g_off[NMAX + 1];
__device__ int   g_cursor[NMAX];
__device__ float g_rdeg[NMAX];
__device__ int2  g_erec[EMAX];                   // {src | rel<<17, w_bits}
__device__ float g_xt[(size_t)NMAX * 320];       // fp32 transformed feats [W0 | Wr0..Wr3]
__device__ float g_h[(size_t)NMAX * 64];         // fp32 hidden state
__device__ float g_agg[(size_t)NMAX * 64];       // fp32 group aggregation

// ---------------- packed fp32x2 helpers ----------------
__device__ __forceinline__ void fma2(unsigned long long &a, unsigned long long x, unsigned long long w) {
    asm("fma.rn.f32x2 %0, %1, %2, %0;" : "+l"(a) : "l"(x), "l"(w));
}
__device__ __forceinline__ unsigned long long pack2(float v) {
    unsigned long long r;
    asm("mov.b64 %0, {%1, %1};" : "=l"(r) : "f"(v));
    return r;
}
__device__ __forceinline__ float2 unpack2(unsigned long long a) {
    float2 f;
    asm("mov.b64 {%0, %1}, %2;" : "=f"(f.x), "=f"(f.y) : "l"(a));
    return f;
}
__device__ __forceinline__ unsigned f2tf32(float v) {
    unsigned r;
    asm("cvt.rna.tf32.f32 %0, %1;" : "=r"(r) : "f"(v));
    return r;
}

// ---------------- degree ----------------
extern "C" __global__ void k_deg(const int* __restrict__ ei, int* __restrict__ cnt, int E) {
    int e = blockIdx.x * blockDim.x + threadIdx.x;
    if (e < E) atomicAdd(&cnt[ei[E + e]], 1);
}

// ---------------- single-pass chained scan: off/cursor/rdeg ----------------
extern "C" __global__ void __launch_bounds__(1024)
k_scanAll(const int* __restrict__ cnt, int* __restrict__ flag, int* __restrict__ pref,
          int* __restrict__ off, int* __restrict__ cursor, float* __restrict__ rdeg,
          int N, int E) {
    __shared__ int wsum[32];
    __shared__ int s_pref;
    int t = threadIdx.x, b = blockIdx.x, g = b * 1024 + t;
    int v = (g < N) ? cnt[g] : 0;
    int lane = t & 31, wid = t >> 5;
    int x = v;
    #pragma unroll
    for (int d = 1; d < 32; d <<= 1) {
        int y = __shfl_up_sync(0xFFFFFFFF, x, d);
        if (lane >= d) x += y;
    }
    if (lane == 31) wsum[wid] = x;
    __syncthreads();
    if (wid == 0) {
        int s = wsum[lane];
        #pragma unroll
        for (int d = 1; d < 32; d <<= 1) {
            int y = __shfl_up_sync(0xFFFFFFFF, s, d);
            if (lane >= d) s += y;
        }
        wsum[lane] = s;
    }
    __syncthreads();
    int incl = x + (wid > 0 ? wsum[wid - 1] : 0);
    if (t == 0) {
        int p = 0;
        if (b > 0) {
            while (atomicAdd(&flag[b - 1], 0) == 0) __nanosleep(40);
            __threadfence();
            p = pref[b - 1];
        }
        s_pref = p;
        pref[b] = p + wsum[31];
        __threadfence();
        atomicExch(&flag[b], 1);
    }
    __syncthreads();
    int base = s_pref;
    if (g < N) {
        int o = base + incl - v;
        off[g] = o;
        cursor[g] = o;
        rdeg[g] = 1.0f / (float)max(v, 1);
    }
    if (g == 0) off[N] = E;
}

extern "C" __global__ void k_fill(const int* __restrict__ ei, const int* __restrict__ et,
                                  const float* __restrict__ ew, int* __restrict__ cursor,
                                  int2* __restrict__ erec, int E) {
    int e = blockIdx.x * blockDim.x + threadIdx.x;
    if (e >= E) return;
    int dst = ei[E + e];
    int pos = atomicAdd(&cursor[dst], 1);
    erec[pos] = make_int2(ei[e] | (et[e] << 17), __float_as_int(ew[e]));
}

// ---------------- transform (tf32 mma): out[N,320] = A[N,64] @ [W0 | Wr0..Wr3] ----------------
// block = 256 thr (8 warps), 128 rows/block. Warp w: rows 16w..16w+15.
// A-frags held in registers across all 5 passes; B (weights) from conflict-free smem.
extern "C" __global__ void __launch_bounds__(256)
k_transform_mma(const float* __restrict__ A, const float* __restrict__ W0,
                const float* __restrict__ Wr, float* __restrict__ out, int N) {
    extern __shared__ unsigned usm[];
    unsigned* xs = usm;              // [128][TXP] tf32 bits
    unsigned* ws = usm + 128 * TXP;  // [64][TWP]  tf32 bits
    int t = threadIdx.x;
    int r0 = blockIdx.x * 128;

    // stage A (tf32-converted), zero-padded
    for (int i = t; i < 128 * 16; i += 256) {
        int row = i >> 4, c4 = (i & 15) << 2;
        int g = r0 + row;
        float4 v = {0.f, 0.f, 0.f, 0.f};
        if (g < N) v = *(const float4*)&A[(size_t)g * 64 + c4];
        uint4 o;
        o.x = f2tf32(v.x); o.y = f2tf32(v.y); o.z = f2tf32(v.z); o.w = f2tf32(v.w);
        *(uint4*)&xs[row * TXP + c4] = o;
    }
    __syncthreads();

    int w = t >> 5, lane = t & 31;
    int gid = lane >> 2, tig = lane & 3;
    int arow = 16 * w + gid;

    // load A fragments (m16n8k8 tf32 layout), once for all passes
    unsigned a[8][4];
    #pragma unroll
    for (int s = 0; s < 8; s++) {
        a[s][0] = xs[arow * TXP + 8 * s + tig];
        a[s][1] = xs[(arow + 8) * TXP + 8 * s + tig];
        a[s][2] = xs[arow * TXP + 8 * s + tig + 4];
        a[s][3] = xs[(arow + 8) * TXP + 8 * s + tig + 4];
    }

    for (int pass = 0; pass < 5; pass++) {
        __syncthreads();
        for (int i = t; i < 64 * 64; i += 256) {
            int k = i >> 6, n = i & 63;
            float v = (pass == 0) ? W0[i] : Wr[(pass - 1) * 4096 + i];
            ws[k * TWP + n] = f2tf32(v);
        }
        __syncthreads();

        #pragma unroll
        for (int nt = 0; nt < 8; nt++) {
            float c0 = 0.f, c1 = 0.f, c2 = 0.f, c3 = 0.f;
            #pragma unroll
            for (int s = 0; s < 8; s++) {
                unsigned b0 = ws[(8 * s + tig) * TWP + nt * 8 + gid];
                unsigned b1 = ws[(8 * s + tig + 4) * TWP + nt * 8 + gid];
                asm("mma.sync.aligned.m16n8k8.row.col.f32.tf32.tf32.f32 "
                    "{%0,%1,%2,%3}, {%4,%5,%6,%7}, {%8,%9}, {%0,%1,%2,%3};"
                    : "+f"(c0), "+f"(c1), "+f"(c2), "+f"(c3)
                    : "r"(a[s][0]), "r"(a[s][1]), "r"(a[s][2]), "r"(a[s][3]),
                      "r"(b0), "r"(b1));
            }
            int gr0 = r0 + arow, gr1 = gr0 + 8;
            int colo = pass * 64 + nt * 8 + 2 * tig;
            if (gr0 < N) *(float2*)&out[(size_t)gr0 * 320 + colo] = make_float2(c0, c1);
            if (gr1 < N) *(float2*)&out[(size_t)gr1 * 320 + colo] = make_float2(c2, c3);
        }
    }
}

// ---------------- RGCN gather (fp32, 4-way unrolled) + fused combine/relu ----------------
extern "C" __global__ void k_rgcn_gather(const int* __restrict__ off, const int2* __restrict__ erec,
                                         const float* __restrict__ xt, const float* __restrict__ rdeg,
                                         float* __restrict__ h, int N) {
    int idx = blockIdx.x * blockDim.x + threadIdx.x;
    int node = idx >> 4;
    if (node >= N) return;
    int lane = idx & 15;
    int beg = __ldg(&off[node]), end = __ldg(&off[node + 1]);
    const float4* xt4 = (const float4*)xt;   // row stride 80 float4s
    float4 a0 = {0,0,0,0}, a1 = {0,0,0,0}, a2 = {0,0,0,0}, a3 = {0,0,0,0};
    int i = beg;
    for (; i + 4 <= end; i += 4) {
        int2 r0 = __ldg(&erec[i]),     r1 = __ldg(&erec[i + 1]);
        int2 r2 = __ldg(&erec[i + 2]), r3 = __ldg(&erec[i + 3]);
        float4 v0 = __ldg(&xt4[(size_t)(r0.x & 0x1FFFF) * 80 + (((r0.x >> 17) + 1) << 4) + lane]);
        float4 v1 = __ldg(&xt4[(size_t)(r1.x & 0x1FFFF) * 80 + (((r1.x >> 17) + 1) << 4) + lane]);
        float4 v2 = __ldg(&xt4[(size_t)(r2.x & 0x1FFFF) * 80 + (((r2.x >> 17) + 1) << 4) + lane]);
        float4 v3 = __ldg(&xt4[(size_t)(r3.x & 0x1FFFF) * 80 + (((r3.x >> 17) + 1) << 4) + lane]);
        float w0 = __int_as_float(r0.y), w1 = __int_as_float(r1.y);
        float w2 = __int_as_float(r2.y), w3 = __int_as_float(r3.y);
        a0.x += w0*v0.x; a0.y += w0*v0.y; a0.z += w0*v0.z; a0.w += w0*v0.w;
        a1.x += w1*v1.x; a1.y += w1*v1.y; a1.z += w1*v1.z; a1.w += w1*v1.w;
        a2.x += w2*v2.x; a2.y += w2*v2.y; a2.z += w2*v2.z; a2.w += w2*v2.w;
        a3.x += w3*v3.x; a3.y += w3*v3.y; a3.z += w3*v3.z; a3.w += w3*v3.w;
    }
    for (; i < end; i++) {
        int2 r0 = __ldg(&erec[i]);
        float w0 = __int_as_float(r0.y);
        float4 v0 = __ldg(&xt4[(size_t)(r0.x & 0x1FFFF) * 80 + (((r0.x >> 17) + 1) << 4) + lane]);
        a0.x += w0*v0.x; a0.y += w0*v0.y; a0.z += w0*v0.z; a0.w += w0*v0.w;
    }
    float4 s = __ldg(&xt4[(size_t)node * 80 + lane]);
    float rd = __ldg(&rdeg[node]);
    float4 o;
    o.x = fmaxf((s.x + (a0.x + a1.x) + (a2.x + a3.x)) * rd, 0.f);
    o.y = fmaxf((s.y + (a0.y + a1.y) + (a2.y + a3.y)) * rd, 0.f);
    o.z = fmaxf((s.z + (a0.z + a1.z) + (a2.z + a3.z)) * rd, 0.f);
    o.w = fmaxf((s.w + (a0.w + a1.w) + (a2.w + a3.w)) * rd, 0.f);
    *(float4*)&h[((size_t)node << 6) + (lane << 2)] = o;
}

// ---------------- Group gather: agg[n] = sum_e w_e * h[src_e] ----------------
extern "C" __global__ void k_group_gather(const int* __restrict__ off, const int2* __restrict__ erec,
                                          const float* __restrict__ h, float* __restrict__ agg, int N) {
    int idx = blockIdx.x * blockDim.x + threadIdx.x;
    int node = idx >> 4;
    if (node >= N) return;
    int lane = idx & 15;
    int beg = __ldg(&off[node]), end = __ldg(&off[node + 1]);
    const float4* h4 = (const float4*)h;     // row stride 16 float4s
    float4 a0 = {0,0,0,0}, a1 = {0,0,0,0}, a2 = {0,0,0,0}, a3 = {0,0,0,0};
    int i = beg;
    for (; i + 4 <= end; i += 4) {
        int2 r0 = __ldg(&erec[i]),     r1 = __ldg(&erec[i + 1]);
        int2 r2 = __ldg(&erec[i + 2]), r3 = __ldg(&erec[i + 3]);
        float4 v0 = __ldg(&h4[(size_t)((r0.x & 0x1FFFF) << 4) + lane]);
        float4 v1 = __ldg(&h4[(size_t)((r1.x & 0x1FFFF) << 4) + lane]);
        float4 v2 = __ldg(&h4[(size_t)((r2.x & 0x1FFFF) << 4) + lane]);
        float4 v3 = __ldg(&h4[(size_t)((r3.x & 0x1FFFF) << 4) + lane]);
        float w0 = __int_as_float(r0.y), w1 = __int_as_float(r1.y);
        float w2 = __int_as_float(r2.y), w3 = __int_as_float(r3.y);
        a0.x += w0*v0.x; a0.y += w0*v0.y; a0.z += w0*v0.z; a0.w += w0*v0.w;
        a1.x += w1*v1.x; a1.y += w1*v1.y; a1.z += w1*v1.z; a1.w += w1*v1.w;
        a2.x += w2*v2.x; a2.y += w2*v2.y; a2.z += w2*v2.z; a2.w += w2*v2.w;
        a3.x += w3*v3.x; a3.y += w3*v3.y; a3.z += w3*v3.z; a3.w += w3*v3.w;
    }
    for (; i < end; i++) {
        int2 r0 = __ldg(&erec[i]);
        float w0 = __int_as_float(r0.y);
        float4 v0 = __ldg(&h4[(size_t)((r0.x & 0x1FFFF) << 4) + lane]);
        a0.x += w0*v0.x; a0.y += w0*v0.y; a0.z += w0*v0.z; a0.w += w0*v0.w;
    }
    float4 o;
    o.x = (a0.x + a1.x) + (a2.x + a3.x);
    o.y = (a0.y + a1.y) + (a2.y + a3.y);
    o.z = (a0.z + a1.z) + (a2.z + a3.z);
    o.w = (a0.w + a1.w) + (a2.w + a3.w);
    *(float4*)&agg[((size_t)node << 6) + (lane << 2)] = o;
}

// ---------------- Group combine: h += alpha * ((agg*rdeg) @ W + b) ----------------
extern "C" __global__ void __launch_bounds__(256)
k_group_combine(const float* __restrict__ agg, const float* __restrict__ rdeg,
                const float* __restrict__ W, const float* __restrict__ b,
                const float* __restrict__ alpha_p, float* __restrict__ h, int N) {
    extern __shared__ float sm[];
    float* xs = sm;              // [64][XS_P]
    float* ws = sm + 64 * XS_P;  // [64][64]
    int t = threadIdx.x;
    int r0 = blockIdx.x * 128;

    for (int i = t; i < 128 * 64; i += 256) {
        int row = i >> 6, k = i & 63;
        int g = r0 + row;
        xs[k * XS_P + row] = (g < N) ? agg[(size_t)g * 64 + k] * rdeg[g] : 0.f;
    }
    for (int i = t; i < 64 * 64; i += 256) ws[i] = W[i];
    __syncthreads();

    float alpha = *alpha_p;
    int tx = t & 7, ty = t >> 3;
    const float* xp = &xs[4 * ty];

    unsigned long long acc[4][4];
    #pragma unroll
    for (int r = 0; r < 4; r++)
        #pragma unroll
        for (int j = 0; j < 4; j++) acc[r][j] = 0ULL;

    #pragma unroll 4
    for (int k = 0; k < 64; k++) {
        float4 xv = *(const float4*)&xp[k * XS_P];
        ulonglong2 wA = *(const ulonglong2*)&ws[k * 64 + 8 * tx];
        ulonglong2 wB = *(const ulonglong2*)&ws[k * 64 + 8 * tx + 4];
        unsigned long long x0 = pack2(xv.x), x1 = pack2(xv.y),
                           x2 = pack2(xv.z), x3 = pack2(xv.w);
        fma2(acc[0][0], x0, wA.x); fma2(acc[0][1], x0, wA.y);
        fma2(acc[0][2], x0, wB.x); fma2(acc[0][3], x0, wB.y);
        fma2(acc[1][0], x1, wA.x); fma2(acc[1][1], x1, wA.y);
        fma2(acc[1][2], x1, wB.x); fma2(acc[1][3], x1, wB.y);
        fma2(acc[2][0], x2, wA.x); fma2(acc[2][1], x2, wA.y);
        fma2(acc[2][2], x2, wB.x); fma2(acc[2][3], x2, wB.y);
        fma2(acc[3][0], x3, wA.x); fma2(acc[3][1], x3, wA.y);
        fma2(acc[3][2], x3, wB.x); fma2(acc[3][3], x3, wB.y);
    }
    float4 b0 = *(const float4*)&b[8 * tx];
    float4 b1 = *(const float4*)&b[8 * tx + 4];
    #pragma unroll
    for (int r = 0; r < 4; r++) {
        int gr = r0 + 4 * ty + r;
        if (gr < N) {
            float* hp = &h[((size_t)gr << 6) + 8 * tx];
            float4 h0 = *(float4*)hp;
            float4 h1 = *(float4*)(hp + 4);
            float2 f0 = unpack2(acc[r][0]), f1 = unpack2(acc[r][1]);
            float2 f2 = unpack2(acc[r][2]), f3 = unpack2(acc[r][3]);
            h0.x += alpha * (f0.x + b0.x); h0.y += alpha * (f0.y + b0.y);
            h0.z += alpha * (f1.x + b0.z); h0.w += alpha * (f1.y + b0.w);
            h1.x += alpha * (f2.x + b1.x); h1.y += alpha * (f2.y + b1.y);
            h1.z += alpha * (f3.x + b1.z); h1.w += alpha * (f3.y + b1.w);
            *(float4*)hp = h0;
            *(float4*)(hp + 4) = h1;
        }
    }
}

// ---------------- Output head: out = h @ outW[64,32] + outb ----------------
extern "C" __global__ void __launch_bounds__(256, 4)
k_head(const float* __restrict__ h, const float* __restrict__ W, const float* __restrict__ b,
       float* __restrict__ out, int N) {
    extern __shared__ float sm[];
    float* xs = sm;              // 128*65
    float* ws = sm + 128 * 65;   // 64*32
    int t = threadIdx.x;
    int r0 = blockIdx.x * 128;
    for (int i = t; i < 128 * 64; i += 256) {
        int rr = i >> 6, k = i & 63;
        int g = r0 + rr;
        xs[rr * 65 + k] = (g < N) ? h[(size_t)g * 64 + k] : 0.f;
    }
    for (int i = t; i < 64 * 32; i += 256) ws[i] = W[i];
    __syncthreads();
    int row = t & 127, th = t >> 7;
    int gr = r0 + row;
    const float* xrow = &xs[row * 65];
    for (int jt = 0; jt < 2; jt++) {
        int jl = (jt * 2 + th) * 8;
        unsigned long long a0 = 0, a1 = 0, a2 = 0, a3 = 0;
        #pragma unroll
        for (int k = 0; k < 64; k++) {
            unsigned long long xv = pack2(xrow[k]);
            const float* wp = &ws[k * 32 + jl];
            ulonglong2 wA = *(const ulonglong2*)wp;
            ulonglong2 wB = *(const ulonglong2*)(wp + 4);
            fma2(a0, xv, wA.x); fma2(a1, xv, wA.y);
            fma2(a2, xv, wB.x); fma2(a3, xv, wB.y);
        }
        if (gr < N) {
            float2 f0 = unpack2(a0), f1 = unpack2(a1), f2 = unpack2(a2), f3 = unpack2(a3);
            const float* bp = &b[jl];
            float* op = &out[(size_t)gr * 32 + jl];
            op[0] = f0.x + bp[0]; op[1] = f0.y + bp[1];
            op[2] = f1.x + bp[2]; op[3] = f1.y + bp[3];
            op[4] = f2.x + bp[4]; op[5] = f2.y + bp[5];
            op[6] = f3.x + bp[6]; op[7] = f3.y + bp[7];
        }
    }
}

// ---------------- launch ----------------
extern "C" void kernel_launch(void* const* d_in, const int* in_sizes, int n_in,
                              void* d_out, int out_size) {
    const float* x      = (const float*)d_in[0];
    const int*   ei     = (const int*)d_in[1];
    const int*   et     = (const int*)d_in[2];
    const float* ew     = (const float*)d_in[3];
    const float* W1     = (const float*)d_in[4];
    const float* W01    = (const float*)d_in[5];
    const float* alpha1 = (const float*)d_in[6];
    const float* projW1 = (const float*)d_in[7];
    const float* projb1 = (const float*)d_in[8];
    const float* W2     = (const float*)d_in[9];
    const float* W02    = (const float*)d_in[10];
    const float* alpha2 = (const float*)d_in[11];
    const float* projW2 = (const float*)d_in[12];
    const float* projb2 = (const float*)d_in[13];
    const float* outW   = (const float*)d_in[14];
    const float* outb   = (const float*)d_in[15];

    int N = in_sizes[0] / 64;
    int E = in_sizes[2];

    float *rdeg, *agg, *xt, *h;
    int *cntflag, *pref, *off, *cursor;
    int2 *erec;
    cudaGetSymbolAddress((void**)&cntflag, g_cntflag);
    cudaGetSymbolAddress((void**)&pref,    g_pref);
    cudaGetSymbolAddress((void**)&off,     g_off);
    cudaGetSymbolAddress((void**)&cursor,  g_cursor);
    cudaGetSymbolAddress((void**)&rdeg,    g_rdeg);
    cudaGetSymbolAddress((void**)&erec,    g_erec);
    cudaGetSymbolAddress((void**)&xt,      g_xt);
    cudaGetSymbolAddress((void**)&h,       g_h);
    cudaGetSymbolAddress((void**)&agg,     g_agg);

    static cudaStream_t s2 = nullptr;
    static cudaEvent_t evFork = nullptr, evJoin = nullptr;
    if (s2 == nullptr) {
        cudaStreamCreateWithFlags(&s2, cudaStreamNonBlocking);
        cudaEventCreateWithFlags(&evFork, cudaEventDisableTiming);
        cudaEventCreateWithFlags(&evJoin, cudaEventDisableTiming);
    }

    const int SMEM_M = (128 * TXP + 64 * TWP) * 4;   // transform_mma: 53248
    const int SMEM_T = (64 * XS_P + 64 * 64) * 4;    // group_combine: 50176
    const int SMEM_H = (128 * 65 + 64 * 32) * 4;     // head: 41472
    cudaFuncSetAttribute(k_transform_mma, cudaFuncAttributeMaxDynamicSharedMemorySize, SMEM_M);
    cudaFuncSetAttribute(k_group_combine, cudaFuncAttributeMaxDynamicSharedMemorySize, SMEM_T);
    cudaFuncSetAttribute(k_head,          cudaFuncAttributeMaxDynamicSharedMemorySize, SMEM_H);

    int ebl  = (E + 255) / 256;
    int gthr = (N * 16 + 255) / 256;
    int gbl  = (N + 127) / 128;
    int B1   = (N + 1023) / 1024;

    // ---- fork: CSR build on s2 first (submissions 1-4), transform L1 on main (5) ----
    cudaEventRecord(evFork, 0);
    cudaStreamWaitEvent(s2, evFork, 0);

    cudaMemsetAsync(cntflag, 0, (size_t)(NMAX + 64) * sizeof(int), s2);
    k_deg<<<ebl, 256, 0, s2>>>(ei, cntflag, E);
    k_scanAll<<<B1, 1024, 0, s2>>>(cntflag, cntflag + NMAX, pref,
                                   off, cursor, rdeg, N, E);
    k_fill<<<ebl, 256, 0, s2>>>(ei, et, ew, cursor, erec, E);
    cudaEventRecord(evJoin, s2);

    k_transform_mma<<<gbl, 256, SMEM_M>>>(x, W01, W1, xt, N);

    cudaStreamWaitEvent(0, evJoin, 0);

    // ---- layer 1 ----
    k_rgcn_gather<<<gthr, 256>>>(off, erec, xt, rdeg, h, N);
    k_group_gather<<<gthr, 256>>>(off, erec, h, agg, N);
    k_group_combine<<<gbl, 256, SMEM_T>>>(agg, rdeg, projW1, projb1, alpha1, h, N);

    // ---- layer 2 ----
    k_transform_mma<<<gbl, 256, SMEM_M>>>(h, W02, W2, xt, N);
    k_rgcn_gather<<<gthr, 256>>>(off, erec, xt, rdeg, h, N);
    k_group_gather<<<gthr, 256>>>(off, erec, h, agg, N);
    k_group_combine<<<gbl, 256, SMEM_T>>>(agg, rdeg, projW2, projb2, alpha2, h, N);

    // ---- head ----
    k_head<<<gbl, 256, SMEM_H>>>(h, outW, outb, (float*)d_out, N);
}

// round 7
// speedup vs baseline: 1.1857x; 1.0043x over previous
#include <cuda_runtime.h>
#include <cstdint>

#define NMAX 50000
#define EMAX 1000000
#define XS_P 132
#define TXP 68     // A-tile smem pitch (tf32 words)

// ---------------- scratch (static device globals; no allocation) ----------------
__device__ int   g_cntflag[NMAX + 64];           // [0,NMAX): deg counts, then scan flags (re-zeroed by k_fill)
__device__ int   g_pref[64];
__device__ int   g_off[NMAX + 1];
__device__ int   g_cursor[NMAX];
__device__ float g_rdeg[NMAX];
__device__ int2  g_erec[EMAX];                   // {src<<8 | rel<<28, w_bits}
__device__ float g_xt[(size_t)NMAX * 320];       // fp32 transformed feats [W0 | Wr0..Wr3]
__device__ float g_h[(size_t)NMAX * 64];         // fp32 hidden state
__device__ float g_agg[(size_t)NMAX * 64];       // fp32 group aggregation

// ---------------- packed fp32x2 helpers ----------------
__device__ __forceinline__ void fma2(unsigned long long &a, unsigned long long x, unsigned long long w) {
    asm("fma.rn.f32x2 %0, %1, %2, %0;" : "+l"(a) : "l"(x), "l"(w));
}
__device__ __forceinline__ unsigned long long pack2(float v) {
    unsigned long long r;
    asm("mov.b64 %0, {%1, %1};" : "=l"(r) : "f"(v));
    return r;
}
__device__ __forceinline__ float2 unpack2(unsigned long long a) {
    float2 f;
    asm("mov.b64 {%0, %1}, %2;" : "=f"(f.x), "=f"(f.y) : "l"(a));
    return f;
}
__device__ __forceinline__ unsigned f2tf32(float v) {
    unsigned r;
    asm("cvt.rna.tf32.f32 %0, %1;" : "=r"(r) : "f"(v));
    return r;
}

// ---------------- degree (2 edges/thread) ----------------
extern "C" __global__ void k_deg(const int* __restrict__ ei, int* __restrict__ cnt, int E) {
    int e2 = blockIdx.x * blockDim.x + threadIdx.x;
    int e = e2 * 2;
    if (e < E) {
        int2 d = *(const int2*)&ei[E + e];
        atomicAdd(&cnt[d.x], 1);
        if (e + 1 < E) atomicAdd(&cnt[d.y], 1);
    }
}

// ---------------- single-pass chained scan: off/cursor/rdeg ----------------
extern "C" __global__ void __launch_bounds__(1024)
k_scanAll(const int* __restrict__ cnt, int* __restrict__ flag, int* __restrict__ pref,
          int* __restrict__ off, int* __restrict__ cursor, float* __restrict__ rdeg,
          int N, int E) {
    __shared__ int wsum[32];
    __shared__ int s_pref;
    int t = threadIdx.x, b = blockIdx.x, g = b * 1024 + t;
    int v = (g < N) ? cnt[g] : 0;
    int lane = t & 31, wid = t >> 5;
    int x = v;
    #pragma unroll
    for (int d = 1; d < 32; d <<= 1) {
        int y = __shfl_up_sync(0xFFFFFFFF, x, d);
        if (lane >= d) x += y;
    }
    if (lane == 31) wsum[wid] = x;
    __syncthreads();
    if (wid == 0) {
        int s = wsum[lane];
        #pragma unroll
        for (int d = 1; d < 32; d <<= 1) {
            int y = __shfl_up_sync(0xFFFFFFFF, s, d);
            if (lane >= d) s += y;
        }
        wsum[lane] = s;
    }
    __syncthreads();
    int incl = x + (wid > 0 ? wsum[wid - 1] : 0);
    if (t == 0) {
        int p = 0;
        if (b > 0) {
            while (atomicAdd(&flag[b - 1], 0) == 0) __nanosleep(40);
            __threadfence();
            p = pref[b - 1];
        }
        s_pref = p;
        pref[b] = p + wsum[31];
        __threadfence();
        atomicExch(&flag[b], 1);
    }
    __syncthreads();
    int base = s_pref;
    if (g < N) {
        int o = base + incl - v;
        off[g] = o;
        cursor[g] = o;
        rdeg[g] = 1.0f / (float)max(v, 1);
    }
    if (g == 0) off[N] = E;
}

// fill CSR edge records; also re-zero cnt+flags for the next graph replay
extern "C" __global__ void k_fill(const int* __restrict__ ei, const int* __restrict__ et,
                                  const float* __restrict__ ew, int* __restrict__ cursor,
                                  int2* __restrict__ erec, int* __restrict__ cntflag, int E) {
    int e = blockIdx.x * blockDim.x + threadIdx.x;
    if (e < NMAX + 64) cntflag[e] = 0;
    if (e >= E) return;
    int dst = ei[E + e];
    int pos = atomicAdd(&cursor[dst], 1);
    erec[pos] = make_int2((ei[e] << 8) | (et[e] << 28), __float_as_int(ew[e]));
}

// ---------------- transform (tf32 mma, frag-major B): out[N,320] = A[N,64] @ [W0|Wr0..3] ----------------
// block = 256 thr (8 warps), 128 rows/block. A-frags in registers across all 5 passes.
// W staged per pass in m16n8k8 B-fragment order: one LDS.64 per mma.
extern "C" __global__ void __launch_bounds__(256)
k_transform_mma(const float* __restrict__ A, const float* __restrict__ W0,
                const float* __restrict__ Wr, float* __restrict__ out, int N) {
    extern __shared__ unsigned usm[];
    unsigned* xs = usm;              // [128][TXP] tf32 bits
    unsigned* ws = usm + 128 * TXP;  // frag-major: [(s*8+nt)*128 + lane*2 + {0,1}]
    int t = threadIdx.x;
    int r0 = blockIdx.x * 128;

    for (int i = t; i < 128 * 16; i += 256) {
        int row = i >> 4, c4 = (i & 15) << 2;
        int g = r0 + row;
        float4 v = {0.f, 0.f, 0.f, 0.f};
        if (g < N) v = *(const float4*)&A[(size_t)g * 64 + c4];
        uint4 o;
        o.x = f2tf32(v.x); o.y = f2tf32(v.y); o.z = f2tf32(v.z); o.w = f2tf32(v.w);
        *(uint4*)&xs[row * TXP + c4] = o;
    }
    __syncthreads();

    int w = t >> 5, lane = t & 31;
    int gid = lane >> 2, tig = lane & 3;
    int arow = 16 * w + gid;

    unsigned a[8][4];
    #pragma unroll
    for (int s = 0; s < 8; s++) {
        a[s][0] = xs[arow * TXP + 8 * s + tig];
        a[s][1] = xs[(arow + 8) * TXP + 8 * s + tig];
        a[s][2] = xs[arow * TXP + 8 * s + tig + 4];
        a[s][3] = xs[(arow + 8) * TXP + 8 * s + tig + 4];
    }

    for (int pass = 0; pass < 5; pass++) {
        const float* Wp = (pass == 0) ? W0 : (Wr + (pass - 1) * 4096);
        __syncthreads();
        for (int i = t; i < 4096; i += 256) {
            int s = i >> 9, nt = (i >> 6) & 7, ln = i & 63;
            int g2 = ln >> 2, t2 = ln & 3;
            int k0 = 8 * s + t2, n = nt * 8 + g2;
            uint2 o;
            o.x = f2tf32(Wp[k0 * 64 + n]);
            o.y = f2tf32(Wp[(k0 + 4) * 64 + n]);
            *(uint2*)&ws[i * 2] = o;
        }
        __syncthreads();

        #pragma unroll
        for (int nt = 0; nt < 8; nt++) {
            float c0 = 0.f, c1 = 0.f, c2 = 0.f, c3 = 0.f;
            #pragma unroll
            for (int s = 0; s < 8; s++) {
                uint2 bb = *(const uint2*)&ws[((s * 8 + nt) << 7) + lane * 2];
                asm("mma.sync.aligned.m16n8k8.row.col.f32.tf32.tf32.f32 "
                    "{%0,%1,%2,%3}, {%4,%5,%6,%7}, {%8,%9}, {%0,%1,%2,%3};"
                    : "+f"(c0), "+f"(c1), "+f"(c2), "+f"(c3)
                    : "r"(a[s][0]), "r"(a[s][1]), "r"(a[s][2]), "r"(a[s][3]),
                      "r"(bb.x), "r"(bb.y));
            }
            int gr0 = r0 + arow, gr1 = gr0 + 8;
            int colo = pass * 64 + nt * 8 + 2 * tig;
            if (gr0 < N) *(float2*)&out[(size_t)gr0 * 320 + colo] = make_float2(c0, c1);
            if (gr1 < N) *(float2*)&out[(size_t)gr1 * 320 + colo] = make_float2(c2, c3);
        }
    }
}

// ---------------- RGCN gather (4-way unrolled, 32-bit offsets) + fused combine/relu ----------------
extern "C" __global__ void k_rgcn_gather(const int* __restrict__ off, const int2* __restrict__ erec,
                                         const float* __restrict__ xt, const float* __restrict__ rdeg,
                                         float* __restrict__ h, int N) {
    int idx = blockIdx.x * blockDim.x + threadIdx.x;
    int node = idx >> 4;
    if (node >= N) return;
    unsigned lo = (unsigned)(idx & 15) << 4;   // lane byte offset
    int beg = __ldg(&off[node]), end = __ldg(&off[node + 1]);
    const char* xb = (const char*)xt;
    float4 a0 = {0,0,0,0}, a1 = {0,0,0,0}, a2 = {0,0,0,0}, a3 = {0,0,0,0};
    int i = beg;
    for (; i + 4 <= end; i += 4) {
        int2 r0 = __ldg(&erec[i]),     r1 = __ldg(&erec[i + 1]);
        int2 r2 = __ldg(&erec[i + 2]), r3 = __ldg(&erec[i + 3]);
        unsigned x0 = r0.x, x1 = r1.x, x2 = r2.x, x3 = r3.x;
        float4 v0 = __ldg((const float4*)(xb + ((x0 & 0x0FFFFFFFu) * 5u + (((x0 >> 28) + 1u) << 8) + lo)));
        float4 v1 = __ldg((const float4*)(xb + ((x1 & 0x0FFFFFFFu) * 5u + (((x1 >> 28) + 1u) << 8) + lo)));
        float4 v2 = __ldg((const float4*)(xb + ((x2 & 0x0FFFFFFFu) * 5u + (((x2 >> 28) + 1u) << 8) + lo)));
        float4 v3 = __ldg((const float4*)(xb + ((x3 & 0x0FFFFFFFu) * 5u + (((x3 >> 28) + 1u) << 8) + lo)));
        float w0 = __int_as_float(r0.y), w1 = __int_as_float(r1.y);
        float w2 = __int_as_float(r2.y), w3 = __int_as_float(r3.y);
        a0.x += w0*v0.x; a0.y += w0*v0.y; a0.z += w0*v0.z; a0.w += w0*v0.w;
        a1.x += w1*v1.x; a1.y += w1*v1.y; a1.z += w1*v1.z; a1.w += w1*v1.w;
        a2.x += w2*v2.x; a2.y += w2*v2.y; a2.z += w2*v2.z; a2.w += w2*v2.w;
        a3.x += w3*v3.x; a3.y += w3*v3.y; a3.z += w3*v3.z; a3.w += w3*v3.w;
    }
    for (; i < end; i++) {
        int2 r0 = __ldg(&erec[i]);
        unsigned x0 = r0.x;
        float w0 = __int_as_float(r0.y);
        float4 v0 = __ldg((const float4*)(xb + ((x0 & 0x0FFFFFFFu) * 5u + (((x0 >> 28) + 1u) << 8) + lo)));
        a0.x += w0*v0.x; a0.y += w0*v0.y; a0.z += w0*v0.z; a0.w += w0*v0.w;
    }
    float4 s = __ldg((const float4*)(xb + ((unsigned)node * 1280u + lo)));
    float rd = __ldg(&rdeg[node]);
    float4 o;
    o.x = fmaxf((s.x + (a0.x + a1.x) + (a2.x + a3.x)) * rd, 0.f);
    o.y = fmaxf((s.y + (a0.y + a1.y) + (a2.y + a3.y)) * rd, 0.f);
    o.z = fmaxf((s.z + (a0.z + a1.z) + (a2.z + a3.z)) * rd, 0.f);
    o.w = fmaxf((s.w + (a0.w + a1.w) + (a2.w + a3.w)) * rd, 0.f);
    *(float4*)((char*)h + ((unsigned)node * 256u + lo)) = o;
}

// ---------------- Group gather: agg[n] = sum_e w_e * h[src_e] ----------------
extern "C" __global__ void k_group_gather(const int* __restrict__ off, const int2* __restrict__ erec,
                                          const float* __restrict__ h, float* __restrict__ agg, int N) {
    int idx = blockIdx.x * blockDim.x + threadIdx.x;
    int node = idx >> 4;
    if (node >= N) return;
    unsigned lo = (unsigned)(idx & 15) << 4;
    int beg = __ldg(&off[node]), end = __ldg(&off[node + 1]);
    const char* hb = (const char*)h;
    float4 a0 = {0,0,0,0}, a1 = {0,0,0,0}, a2 = {0,0,0,0}, a3 = {0,0,0,0};
    int i = beg;
    for (; i + 4 <= end; i += 4) {
        int2 r0 = __ldg(&erec[i]),     r1 = __ldg(&erec[i + 1]);
        int2 r2 = __ldg(&erec[i + 2]), r3 = __ldg(&erec[i + 3]);
        float4 v0 = __ldg((const float4*)(hb + (((unsigned)r0.x & 0x0FFFFFFFu) + lo)));
        float4 v1 = __ldg((const float4*)(hb + (((unsigned)r1.x & 0x0FFFFFFFu) + lo)));
        float4 v2 = __ldg((const float4*)(hb + (((unsigned)r2.x & 0x0FFFFFFFu) + lo)));
        float4 v3 = __ldg((const float4*)(hb + (((unsigned)r3.x & 0x0FFFFFFFu) + lo)));
        float w0 = __int_as_float(r0.y), w1 = __int_as_float(r1.y);
        float w2 = __int_as_float(r2.y), w3 = __int_as_float(r3.y);
        a0.x += w0*v0.x; a0.y += w0*v0.y; a0.z += w0*v0.z; a0.w += w0*v0.w;
        a1.x += w1*v1.x; a1.y += w1*v1.y; a1.z += w1*v1.z; a1.w += w1*v1.w;
        a2.x += w2*v2.x; a2.y += w2*v2.y; a2.z += w2*v2.z; a2.w += w2*v2.w;
        a3.x += w3*v3.x; a3.y += w3*v3.y; a3.z += w3*v3.z; a3.w += w3*v3.w;
    }
    for (; i < end; i++) {
        int2 r0 = __ldg(&erec[i]);
        float w0 = __int_as_float(r0.y);
        float4 v0 = __ldg((const float4*)(hb + (((unsigned)r0.x & 0x0FFFFFFFu) + lo)));
        a0.x += w0*v0.x; a0.y += w0*v0.y; a0.z += w0*v0.z; a0.w += w0*v0.w;
    }
    float4 o;
    o.x = (a0.x + a1.x) + (a2.x + a3.x);
    o.y = (a0.y + a1.y) + (a2.y + a3.y);
    o.z = (a0.z + a1.z) + (a2.z + a3.z);
    o.w = (a0.w + a1.w) + (a2.w + a3.w);
    *(float4*)((char*)agg + ((unsigned)node * 256u + lo)) = o;
}

// ---------------- Group combine: h += alpha * ((agg*rdeg) @ W + b) ----------------
extern "C" __global__ void __launch_bounds__(256)
k_group_combine(const float* __restrict__ agg, const float* __restrict__ rdeg,
                const float* __restrict__ W, const float* __restrict__ b,
                const float* __restrict__ alpha_p, float* __restrict__ h, int N) {
    extern __shared__ float sm[];
    float* xs = sm;              // [64][XS_P]
    float* ws = sm + 64 * XS_P;  // [64][64]
    int t = threadIdx.x;
    int r0 = blockIdx.x * 128;

    for (int i = t; i < 128 * 64; i += 256) {
        int row = i >> 6, k = i & 63;
        int g = r0 + row;
        xs[k * XS_P + row] = (g < N) ? agg[(size_t)g * 64 + k] * rdeg[g] : 0.f;
    }
    for (int i = t; i < 64 * 64; i += 256) ws[i] = W[i];
    __syncthreads();

    float alpha = *alpha_p;
    int tx = t & 7, ty = t >> 3;
    const float* xp = &xs[4 * ty];

    unsigned long long acc[4][4];
    #pragma unroll
    for (int r = 0; r < 4; r++)
        #pragma unroll
        for (int j = 0; j < 4; j++) acc[r][j] = 0ULL;

    #pragma unroll 4
    for (int k = 0; k < 64; k++) {
        float4 xv = *(const float4*)&xp[k * XS_P];
        ulonglong2 wA = *(const ulonglong2*)&ws[k * 64 + 8 * tx];
        ulonglong2 wB = *(const ulonglong2*)&ws[k * 64 + 8 * tx + 4];
        unsigned long long x0 = pack2(xv.x), x1 = pack2(xv.y),
                           x2 = pack2(xv.z), x3 = pack2(xv.w);
        fma2(acc[0][0], x0, wA.x); fma2(acc[0][1], x0, wA.y);
        fma2(acc[0][2], x0, wB.x); fma2(acc[0][3], x0, wB.y);
        fma2(acc[1][0], x1, wA.x); fma2(acc[1][1], x1, wA.y);
        fma2(acc[1][2], x1, wB.x); fma2(acc[1][3], x1, wB.y);
        fma2(acc[2][0], x2, wA.x); fma2(acc[2][1], x2, wA.y);
        fma2(acc[2][2], x2, wB.x); fma2(acc[2][3], x2, wB.y);
        fma2(acc[3][0], x3, wA.x); fma2(acc[3][1], x3, wA.y);
        fma2(acc[3][2], x3, wB.x); fma2(acc[3][3], x3, wB.y);
    }
    float4 b0 = *(const float4*)&b[8 * tx];
    float4 b1 = *(const float4*)&b[8 * tx + 4];
    #pragma unroll
    for (int r = 0; r < 4; r++) {
        int gr = r0 + 4 * ty + r;
        if (gr < N) {
            float* hp = &h[((size_t)gr << 6) + 8 * tx];
            float4 h0 = *(float4*)hp;
            float4 h1 = *(float4*)(hp + 4);
            float2 f0 = unpack2(acc[r][0]), f1 = unpack2(acc[r][1]);
            float2 f2 = unpack2(acc[r][2]), f3 = unpack2(acc[r][3]);
            h0.x += alpha * (f0.x + b0.x); h0.y += alpha * (f0.y + b0.y);
            h0.z += alpha * (f1.x + b0.z); h0.w += alpha * (f1.y + b0.w);
            h1.x += alpha * (f2.x + b1.x); h1.y += alpha * (f2.y + b1.y);
            h1.z += alpha * (f3.x + b1.z); h1.w += alpha * (f3.y + b1.w);
            *(float4*)hp = h0;
            *(float4*)(hp + 4) = h1;
        }
    }
}

// ---------------- Output head: out = h @ outW[64,32] + outb ----------------
extern "C" __global__ void __launch_bounds__(256, 4)
k_head(const float* __restrict__ h, const float* __restrict__ W, const float* __restrict__ b,
       float* __restrict__ out, int N) {
    extern __shared__ float sm[];
    float* xs = sm;              // 128*65
    float* ws = sm + 128 * 65;   // 64*32
    int t = threadIdx.x;
    int r0 = blockIdx.x * 128;
    for (int i = t; i < 128 * 64; i += 256) {
        int rr = i >> 6, k = i & 63;
        int g = r0 + rr;
        xs[rr * 65 + k] = (g < N) ? h[(size_t)g * 64 + k] : 0.f;
    }
    for (int i = t; i < 64 * 32; i += 256) ws[i] = W[i];
    __syncthreads();
    int row = t & 127, th = t >> 7;
    int gr = r0 + row;
    const float* xrow = &xs[row * 65];
    for (int jt = 0; jt < 2; jt++) {
        int jl = (jt * 2 + th) * 8;
        unsigned long long a0 = 0, a1 = 0, a2 = 0, a3 = 0;
        #pragma unroll
        for (int k = 0; k < 64; k++) {
            unsigned long long xv = pack2(xrow[k]);
            const float* wp = &ws[k * 32 + jl];
            ulonglong2 wA = *(const ulonglong2*)wp;
            ulonglong2 wB = *(const ulonglong2*)(wp + 4);
            fma2(a0, xv, wA.x); fma2(a1, xv, wA.y);
            fma2(a2, xv, wB.x); fma2(a3, xv, wB.y);
        }
        if (gr < N) {
            float2 f0 = unpack2(a0), f1 = unpack2(a1), f2 = unpack2(a2), f3 = unpack2(a3);
            const float* bp = &b[jl];
            float* op = &out[(size_t)gr * 32 + jl];
            op[0] = f0.x + bp[0]; op[1] = f0.y + bp[1];
            op[2] = f1.x + bp[2]; op[3] = f1.y + bp[3];
            op[4] = f2.x + bp[4]; op[5] = f2.y + bp[5];
            op[6] = f3.x + bp[6]; op[7] = f3.y + bp[7];
        }
    }
}

// ---------------- launch ----------------
extern "C" void kernel_launch(void* const* d_in, const int* in_sizes, int n_in,
                              void* d_out, int out_size) {
    const float* x      = (const float*)d_in[0];
    const int*   ei     = (const int*)d_in[1];
    const int*   et     = (const int*)d_in[2];
    const float* ew     = (const float*)d_in[3];
    const float* W1     = (const float*)d_in[4];
    const float* W01    = (const float*)d_in[5];
    const float* alpha1 = (const float*)d_in[6];
    const float* projW1 = (const float*)d_in[7];
    const float* projb1 = (const float*)d_in[8];
    const float* W2     = (const float*)d_in[9];
    const float* W02    = (const float*)d_in[10];
    const float* alpha2 = (const float*)d_in[11];
    const float* projW2 = (const float*)d_in[12];
    const float* projb2 = (const float*)d_in[13];
    const float* outW   = (const float*)d_in[14];
    const float* outb   = (const float*)d_in[15];

    int N = in_sizes[0] / 64;
    int E = in_sizes[2];

    float *rdeg, *agg, *xt, *h;
    int *cntflag, *pref, *off, *cursor;
    int2 *erec;
    cudaGetSymbolAddress((void**)&cntflag, g_cntflag);
    cudaGetSymbolAddress((void**)&pref,    g_pref);
    cudaGetSymbolAddress((void**)&off,     g_off);
    cudaGetSymbolAddress((void**)&cursor,  g_cursor);
    cudaGetSymbolAddress((void**)&rdeg,    g_rdeg);
    cudaGetSymbolAddress((void**)&erec,    g_erec);
    cudaGetSymbolAddress((void**)&xt,      g_xt);
    cudaGetSymbolAddress((void**)&h,       g_h);
    cudaGetSymbolAddress((void**)&agg,     g_agg);

    static cudaStream_t s2 = nullptr;
    static cudaEvent_t evFork = nullptr, evJoin = nullptr;
    if (s2 == nullptr) {
        cudaStreamCreateWithFlags(&s2, cudaStreamNonBlocking);
        cudaEventCreateWithFlags(&evFork, cudaEventDisableTiming);
        cudaEventCreateWithFlags(&evJoin, cudaEventDisableTiming);
    }

    const int SMEM_M = (128 * TXP + 8192) * 4;       // transform_mma: 67584
    const int SMEM_T = (64 * XS_P + 64 * 64) * 4;    // group_combine: 50176
    const int SMEM_H = (128 * 65 + 64 * 32) * 4;     // head: 41472
    cudaFuncSetAttribute(k_transform_mma, cudaFuncAttributeMaxDynamicSharedMemorySize, SMEM_M);
    cudaFuncSetAttribute(k_group_combine, cudaFuncAttributeMaxDynamicSharedMemorySize, SMEM_T);
    cudaFuncSetAttribute(k_head,          cudaFuncAttributeMaxDynamicSharedMemorySize, SMEM_H);

    int ebl  = (E + 255) / 256;
    int e2bl = (E / 2 + 255) / 256;
    int gthr = (N * 16 + 255) / 256;
    int gbl  = (N + 127) / 128;
    int B1   = (N + 1023) / 1024;

    // ---- fork: CSR build on s2 (launches 1-3), transform L1 on main (4) ----
    // cntflag starts zeroed (device globals) and is re-zeroed by k_fill each run.
    cudaEventRecord(evFork, 0);
    cudaStreamWaitEvent(s2, evFork, 0);

    k_deg<<<e2bl, 256, 0, s2>>>(ei, cntflag, E);                            // 1
    k_scanAll<<<B1, 1024, 0, s2>>>(cntflag, cntflag + NMAX, pref,
                                   off, cursor, rdeg, N, E);                // 2
    k_fill<<<ebl, 256, 0, s2>>>(ei, et, ew, cursor, erec, cntflag, E);      // 3
    cudaEventRecord(evJoin, s2);

    k_transform_mma<<<gbl, 256, SMEM_M>>>(x, W01, W1, xt, N);               // 4

    cudaStreamWaitEvent(0, evJoin, 0);

    // ---- layer 1 ----
    k_rgcn_gather<<<gthr, 256>>>(off, erec, xt, rdeg, h, N);                // 5 <- ncu capture
    k_group_gather<<<gthr, 256>>>(off, erec, h, agg, N);
    k_group_combine<<<gbl, 256, SMEM_T>>>(agg, rdeg, projW1, projb1, alpha1, h, N);

    // ---- layer 2 ----
    k_transform_mma<<<gbl, 256, SMEM_M>>>(h, W02, W2, xt, N);
    k_rgcn_gather<<<gthr, 256>>>(off, erec, xt, rdeg, h, N);
    k_group_gather<<<gthr, 256>>>(off, erec, h, agg, N);
    k_group_combine<<<gbl, 256, SMEM_T>>>(agg, rdeg, projW2, projb2, alpha2, h, N);

    // ---- head ----
    k_head<<<gbl, 256, SMEM_H>>>(h, outW, outb, (float*)d_out, N);
}

// round 9
// speedup vs baseline: 1.2379x; 1.0440x over previous
#include <cuda_runtime.h>
#include <cstdint>

#define NMAX 50000
#define EMAX 1000000
#define XS_P 132
#define TXP 68     // A-tile smem pitch (tf32 words)

// ---------------- scratch (static device globals; no allocation) ----------------
__device__ int      g_cntflag[NMAX + 64];        // deg counts + scan flags (re-zeroed by k_fill)
__device__ int      g_pref[64];
__device__ int      g_off[NMAX + 1];
__device__ int      g_cursor[NMAX];
__device__ float    g_rdeg[NMAX];
__device__ int2     g_erec[EMAX];                // {src<<8 | rel<<28, w_bits}
__device__ float    g_xt[(size_t)NMAX * 320];    // fp32 transformed feats [W0 | Wr0..Wr3]
__device__ float    g_h[(size_t)NMAX * 64];      // fp32 hidden state
__device__ float    g_agg[(size_t)NMAX * 64];    // fp32 group aggregation
__device__ unsigned g_wfrag[2 * 5 * 4096];       // tf32 frag-major weights (dense 64 words/frag), both layers

// ---------------- packed fp32x2 helpers ----------------
__device__ __forceinline__ void fma2(unsigned long long &a, unsigned long long x, unsigned long long w) {
    asm("fma.rn.f32x2 %0, %1, %2, %0;" : "+l"(a) : "l"(x), "l"(w));
}
__device__ __forceinline__ unsigned long long pack2(float v) {
    unsigned long long r;
    asm("mov.b64 %0, {%1, %1};" : "=l"(r) : "f"(v));
    return r;
}
__device__ __forceinline__ float2 unpack2(unsigned long long a) {
    float2 f;
    asm("mov.b64 {%0, %1}, %2;" : "=f"(f.x), "=f"(f.y) : "l"(a));
    return f;
}
__device__ __forceinline__ unsigned f2tf32(float v) {
    unsigned r;
    asm("cvt.rna.tf32.f32 %0, %1;" : "=r"(r) : "f"(v));
    return r;
}

// ---------------- weight pre-conversion: fp32 [64][64] -> tf32 frag-major (dense) ----------------
// element B[k][n]: s=k>>3, kr=k&7, tig=kr&3, c=kr>>2 (0: k=8s+tig, 1: k=8s+4+tig)
// n: nt=n>>3, gid=n&7, lane=gid*4+tig
// dst = (s*8+nt)*64 + lane*2 + c   (max 4095)
extern "C" __global__ void k_wprep(const float* __restrict__ W01, const float* __restrict__ W1,
                                   const float* __restrict__ W02, const float* __restrict__ W2,
                                   unsigned* __restrict__ wfrag) {
    int i = blockIdx.x * blockDim.x + threadIdx.x;   // 0 .. 40959
    if (i >= 2 * 5 * 4096) return;
    int L = i / 20480;
    int rem = i - L * 20480;
    int p = rem >> 12, j = rem & 4095;
    const float* W0 = L ? W02 : W01;
    const float* Wr = L ? W2 : W1;
    float v = (p == 0) ? W0[j] : Wr[(p - 1) * 4096 + j];
    int k = j >> 6, n = j & 63;
    int s = k >> 3, kr = k & 7;
    int tig = kr & 3, c = kr >> 2;
    int nt = n >> 3, gid = n & 7;
    int lane = gid * 4 + tig;
    int dst = ((s * 8 + nt) << 6) + (lane << 1) + c;
    wfrag[L * 20480 + (p << 12) + dst] = f2tf32(v);
}

// ---------------- degree (2 edges/thread) ----------------
extern "C" __global__ void k_deg(const int* __restrict__ ei, int* __restrict__ cnt, int E) {
    int e2 = blockIdx.x * blockDim.x + threadIdx.x;
    int e = e2 * 2;
    if (e < E) {
        int2 d = *(const int2*)&ei[E + e];
        atomicAdd(&cnt[d.x], 1);
        if (e + 1 < E) atomicAdd(&cnt[d.y], 1);
    }
}

// ---------------- single-pass chained scan ----------------
extern "C" __global__ void __launch_bounds__(1024)
k_scanAll(const int* __restrict__ cnt, int* __restrict__ flag, int* __restrict__ pref,
          int* __restrict__ off, int* __restrict__ cursor, float* __restrict__ rdeg,
          int N, int E) {
    __shared__ int wsum[32];
    __shared__ int s_pref;
    int t = threadIdx.x, b = blockIdx.x, g = b * 1024 + t;
    int v = (g < N) ? cnt[g] : 0;
    int lane = t & 31, wid = t >> 5;
    int x = v;
    #pragma unroll
    for (int d = 1; d < 32; d <<= 1) {
        int y = __shfl_up_sync(0xFFFFFFFF, x, d);
        if (lane >= d) x += y;
    }
    if (lane == 31) wsum[wid] = x;
    __syncthreads();
    if (wid == 0) {
        int s = wsum[lane];
        #pragma unroll
        for (int d = 1; d < 32; d <<= 1) {
            int y = __shfl_up_sync(0xFFFFFFFF, s, d);
            if (lane >= d) s += y;
        }
        wsum[lane] = s;
    }
    __syncthreads();
    int incl = x + (wid > 0 ? wsum[wid - 1] : 0);
    if (t == 0) {
        int p = 0;
        if (b > 0) {
            while (atomicAdd(&flag[b - 1], 0) == 0) __nanosleep(40);
            __threadfence();
            p = pref[b - 1];
        }
        s_pref = p;
        pref[b] = p + wsum[31];
        __threadfence();
        atomicExch(&flag[b], 1);
    }
    __syncthreads();
    int base = s_pref;
    if (g < N) {
        int o = base + incl - v;
        off[g] = o;
        cursor[g] = o;
        rdeg[g] = 1.0f / (float)max(v, 1);
    }
    if (g == 0) off[N] = E;
}

// fill CSR edge records; re-zero cnt+flags for the next graph replay
extern "C" __global__ void k_fill(const int* __restrict__ ei, const int* __restrict__ et,
                                  const float* __restrict__ ew, int* __restrict__ cursor,
                                  int2* __restrict__ erec, int* __restrict__ cntflag, int E) {
    int e = blockIdx.x * blockDim.x + threadIdx.x;
    if (e < NMAX + 64) cntflag[e] = 0;
    if (e >= E) return;
    int dst = ei[E + e];
    int pos = atomicAdd(&cursor[dst], 1);
    erec[pos] = make_int2((ei[e] << 8) | (et[e] << 28), __float_as_int(ew[e]));
}

// ---------------- transform (tf32 mma, cp.async double-buffered dense frag-major W) ----------------
extern "C" __global__ void __launch_bounds__(256)
k_transform_mma(const float* __restrict__ A, const unsigned* __restrict__ wfrag,
                float* __restrict__ out, int N) {
    extern __shared__ unsigned usm[];
    unsigned* xs = usm;               // [128][TXP] A tf32 bits
    unsigned* wsb = usm + 128 * TXP;  // 2 x 4096 dense frag-major W buffers
    int t = threadIdx.x;
    int r0 = blockIdx.x * 128;

    // issue W copy for pass 0 (coalesced, 4 x 16B per thread = 4096 words total)
    {
        unsigned sdst = (unsigned)__cvta_generic_to_shared(&wsb[t * 4]);
        const unsigned* gsrc = wfrag + t * 4;
        #pragma unroll
        for (int c = 0; c < 4; c++) {
            asm volatile("cp.async.cg.shared.global [%0], [%1], 16;"
                         :: "r"(sdst + c * 4096), "l"(gsrc + c * 1024));
        }
        asm volatile("cp.async.commit_group;");
    }

    // stage A (tf32) while copy flies
    for (int i = t; i < 128 * 16; i += 256) {
        int row = i >> 4, c4 = (i & 15) << 2;
        int g = r0 + row;
        float4 v = {0.f, 0.f, 0.f, 0.f};
        if (g < N) v = *(const float4*)&A[(size_t)g * 64 + c4];
        uint4 o;
        o.x = f2tf32(v.x); o.y = f2tf32(v.y); o.z = f2tf32(v.z); o.w = f2tf32(v.w);
        *(uint4*)&xs[row * TXP + c4] = o;
    }
    __syncthreads();

    int w = t >> 5, lane = t & 31;
    int gid = lane >> 2, tig = lane & 3;
    int arow = 16 * w + gid;

    unsigned a[8][4];
    #pragma unroll
    for (int s = 0; s < 8; s++) {
        a[s][0] = xs[arow * TXP + 8 * s + tig];
        a[s][1] = xs[(arow + 8) * TXP + 8 * s + tig];
        a[s][2] = xs[arow * TXP + 8 * s + tig + 4];
        a[s][3] = xs[(arow + 8) * TXP + 8 * s + tig + 4];
    }

    for (int pass = 0; pass < 5; pass++) {
        asm volatile("cp.async.wait_group 0;");
        __syncthreads();                         // copy(pass) visible; compute(pass-1) done everywhere
        if (pass < 4) {                          // prefetch next pass into the other buffer
            unsigned* dstb = &wsb[((pass + 1) & 1) * 4096];
            unsigned sdst = (unsigned)__cvta_generic_to_shared(&dstb[t * 4]);
            const unsigned* gsrc = wfrag + (pass + 1) * 4096 + t * 4;
            #pragma unroll
            for (int c = 0; c < 4; c++) {
                asm volatile("cp.async.cg.shared.global [%0], [%1], 16;"
                             :: "r"(sdst + c * 4096), "l"(gsrc + c * 1024));
            }
            asm volatile("cp.async.commit_group;");
        }
        const unsigned* ws = &wsb[(pass & 1) * 4096];

        #pragma unroll
        for (int nt = 0; nt < 8; nt++) {
            float c0 = 0.f, c1 = 0.f, c2 = 0.f, c3 = 0.f;
            #pragma unroll
            for (int s = 0; s < 8; s++) {
                uint2 bb = *(const uint2*)&ws[((s * 8 + nt) << 6) + lane * 2];
                asm("mma.sync.aligned.m16n8k8.row.col.f32.tf32.tf32.f32 "
                    "{%0,%1,%2,%3}, {%4,%5,%6,%7}, {%8,%9}, {%0,%1,%2,%3};"
                    : "+f"(c0), "+f"(c1), "+f"(c2), "+f"(c3)
                    : "r"(a[s][0]), "r"(a[s][1]), "r"(a[s][2]), "r"(a[s][3]),
                      "r"(bb.x), "r"(bb.y));
            }
            int gr0 = r0 + arow, gr1 = gr0 + 8;
            int colo = pass * 64 + nt * 8 + 2 * tig;
            if (gr0 < N) *(float2*)&out[(size_t)gr0 * 320 + colo] = make_float2(c0, c1);
            if (gr1 < N) *(float2*)&out[(size_t)gr1 * 320 + colo] = make_float2(c2, c3);
        }
    }
}

// ---------------- RGCN gather (4-way unrolled, 32-bit offsets) + fused combine/relu ----------------
extern "C" __global__ void k_rgcn_gather(const int* __restrict__ off, const int2* __restrict__ erec,
                                         const float* __restrict__ xt, const float* __restrict__ rdeg,
                                         float* __restrict__ h, int N) {
    int idx = blockIdx.x * blockDim.x + threadIdx.x;
    int node = idx >> 4;
    if (node >= N) return;
    unsigned lo = (unsigned)(idx & 15) << 4;
    int beg = __ldg(&off[node]), end = __ldg(&off[node + 1]);
    const char* xb = (const char*)xt;
    float4 a0 = {0,0,0,0}, a1 = {0,0,0,0}, a2 = {0,0,0,0}, a3 = {0,0,0,0};
    int i = beg;
    for (; i + 4 <= end; i += 4) {
        int2 r0 = __ldg(&erec[i]),     r1 = __ldg(&erec[i + 1]);
        int2 r2 = __ldg(&erec[i + 2]), r3 = __ldg(&erec[i + 3]);
        unsigned x0 = r0.x, x1 = r1.x, x2 = r2.x, x3 = r3.x;
        float4 v0 = __ldg((const float4*)(xb + ((x0 & 0x0FFFFFFFu) * 5u + (((x0 >> 28) + 1u) << 8) + lo)));
        float4 v1 = __ldg((const float4*)(xb + ((x1 & 0x0FFFFFFFu) * 5u + (((x1 >> 28) + 1u) << 8) + lo)));
        float4 v2 = __ldg((const float4*)(xb + ((x2 & 0x0FFFFFFFu) * 5u + (((x2 >> 28) + 1u) << 8) + lo)));
        float4 v3 = __ldg((const float4*)(xb + ((x3 & 0x0FFFFFFFu) * 5u + (((x3 >> 28) + 1u) << 8) + lo)));
        float w0 = __int_as_float(r0.y), w1 = __int_as_float(r1.y);
        float w2 = __int_as_float(r2.y), w3 = __int_as_float(r3.y);
        a0.x += w0*v0.x; a0.y += w0*v0.y; a0.z += w0*v0.z; a0.w += w0*v0.w;
        a1.x += w1*v1.x; a1.y += w1*v1.y; a1.z += w1*v1.z; a1.w += w1*v1.w;
        a2.x += w2*v2.x; a2.y += w2*v2.y; a2.z += w2*v2.z; a2.w += w2*v2.w;
        a3.x += w3*v3.x; a3.y += w3*v3.y; a3.z += w3*v3.z; a3.w += w3*v3.w;
    }
    for (; i < end; i++) {
        int2 r0 = __ldg(&erec[i]);
        unsigned x0 = r0.x;
        float w0 = __int_as_float(r0.y);
        float4 v0 = __ldg((const float4*)(xb + ((x0 & 0x0FFFFFFFu) * 5u + (((x0 >> 28) + 1u) << 8) + lo)));
        a0.x += w0*v0.x; a0.y += w0*v0.y; a0.z += w0*v0.z; a0.w += w0*v0.w;
    }
    float4 s = __ldg((const float4*)(xb + ((unsigned)node * 1280u + lo)));
    float rd = __ldg(&rdeg[node]);
    float4 o;
    o.x = fmaxf((s.x + (a0.x + a1.x) + (a2.x + a3.x)) * rd, 0.f);
    o.y = fmaxf((s.y + (a0.y + a1.y) + (a2.y + a3.y)) * rd, 0.f);
    o.z = fmaxf((s.z + (a0.z + a1.z) + (a2.z + a3.z)) * rd, 0.f);
    o.w = fmaxf((s.w + (a0.w + a1.w) + (a2.w + a3.w)) * rd, 0.f);
    *(float4*)((char*)h + ((unsigned)node * 256u + lo)) = o;
}

// ---------------- Group gather: agg[n] = sum_e w_e * h[src_e] ----------------
extern "C" __global__ void k_group_gather(const int* __restrict__ off, const int2* __restrict__ erec,
                                          const float* __restrict__ h, float* __restrict__ agg, int N) {
    int idx = blockIdx.x * blockDim.x + threadIdx.x;
    int node = idx >> 4;
    if (node >= N) return;
    unsigned lo = (unsigned)(idx & 15) << 4;
    int beg = __ldg(&off[node]), end = __ldg(&off[node + 1]);
    const char* hb = (const char*)h;
    float4 a0 = {0,0,0,0}, a1 = {0,0,0,0}, a2 = {0,0,0,0}, a3 = {0,0,0,0};
    int i = beg;
    for (; i + 4 <= end; i += 4) {
        int2 r0 = __ldg(&erec[i]),     r1 = __ldg(&erec[i + 1]);
        int2 r2 = __ldg(&erec[i + 2]), r3 = __ldg(&erec[i + 3]);
        float4 v0 = __ldg((const float4*)(hb + (((unsigned)r0.x & 0x0FFFFFFFu) + lo)));
        float4 v1 = __ldg((const float4*)(hb + (((unsigned)r1.x & 0x0FFFFFFFu) + lo)));
        float4 v2 = __ldg((const float4*)(hb + (((unsigned)r2.x & 0x0FFFFFFFu) + lo)));
        float4 v3 = __ldg((const float4*)(hb + (((unsigned)r3.x & 0x0FFFFFFFu) + lo)));
        float w0 = __int_as_float(r0.y), w1 = __int_as_float(r1.y);
        float w2 = __int_as_float(r2.y), w3 = __int_as_float(r3.y);
        a0.x += w0*v0.x; a0.y += w0*v0.y; a0.z += w0*v0.z; a0.w += w0*v0.w;
        a1.x += w1*v1.x; a1.y += w1*v1.y; a1.z += w1*v1.z; a1.w += w1*v1.w;
        a2.x += w2*v2.x; a2.y += w2*v2.y; a2.z += w2*v2.z; a2.w += w2*v2.w;
        a3.x += w3*v3.x; a3.y += w3*v3.y; a3.z += w3*v3.z; a3.w += w3*v3.w;
    }
    for (; i < end; i++) {
        int2 r0 = __ldg(&erec[i]);
        float w0 = __int_as_float(r0.y);
        float4 v0 = __ldg((const float4*)(hb + (((unsigned)r0.x & 0x0FFFFFFFu) + lo)));
        a0.x += w0*v0.x; a0.y += w0*v0.y; a0.z += w0*v0.z; a0.w += w0*v0.w;
    }
    float4 o;
    o.x = (a0.x + a1.x) + (a2.x + a3.x);
    o.y = (a0.y + a1.y) + (a2.y + a3.y);
    o.z = (a0.z + a1.z) + (a2.z + a3.z);
    o.w = (a0.w + a1.w) + (a2.w + a3.w);
    *(float4*)((char*)agg + ((unsigned)node * 256u + lo)) = o;
}

// ---------------- Group combine core ----------------
// HEAD=0: h += alpha*((agg*rdeg)@W + b), write h to global.
// HEAD=1: additionally compute out = h_final @ outW + outb via smem handoff; h not written.
template <int HEAD>
__device__ __forceinline__ void group_combine_impl(
    const float* __restrict__ agg, const float* __restrict__ rdeg,
    const float* __restrict__ W, const float* __restrict__ b,
    const float* __restrict__ alpha_p, float* __restrict__ h,
    const float* __restrict__ outW, const float* __restrict__ outb,
    float* __restrict__ out, int N) {
    extern __shared__ float sm[];
    float* xs = sm;                      // [64][XS_P] GEMM input; reused as xh [128][65] in HEAD phase
    float* ws = sm + 64 * XS_P;          // [64][64] proj W
    float* ws2 = ws + 64 * 64;           // [64][32] outW (HEAD only)
    int t = threadIdx.x;
    int r0 = blockIdx.x * 128;

    for (int i = t; i < 128 * 64; i += 256) {
        int row = i >> 6, k = i & 63;
        int g = r0 + row;
        xs[k * XS_P + row] = (g < N) ? agg[(size_t)g * 64 + k] * rdeg[g] : 0.f;
    }
    for (int i = t; i < 64 * 64; i += 256) ws[i] = W[i];
    if (HEAD) for (int i = t; i < 64 * 32; i += 256) ws2[i] = outW[i];
    __syncthreads();

    float alpha = *alpha_p;
    int tx = t & 7, ty = t >> 3;
    const float* xp = &xs[4 * ty];

    unsigned long long acc[4][4];
    #pragma unroll
    for (int r = 0; r < 4; r++)
        #pragma unroll
        for (int j = 0; j < 4; j++) acc[r][j] = 0ULL;

    #pragma unroll 4
    for (int k = 0; k < 64; k++) {
        float4 xv = *(const float4*)&xp[k * XS_P];
        ulonglong2 wA = *(const ulonglong2*)&ws[k * 64 + 8 * tx];
        ulonglong2 wB = *(const ulonglong2*)&ws[k * 64 + 8 * tx + 4];
        unsigned long long x0 = pack2(xv.x), x1 = pack2(xv.y),
                           x2 = pack2(xv.z), x3 = pack2(xv.w);
        fma2(acc[0][0], x0, wA.x); fma2(acc[0][1], x0, wA.y);
        fma2(acc[0][2], x0, wB.x); fma2(acc[0][3], x0, wB.y);
        fma2(acc[1][0], x1, wA.x); fma2(acc[1][1], x1, wA.y);
        fma2(acc[1][2], x1, wB.x); fma2(acc[1][3], x1, wB.y);
        fma2(acc[2][0], x2, wA.x); fma2(acc[2][1], x2, wA.y);
        fma2(acc[2][2], x2, wB.x); fma2(acc[2][3], x2, wB.y);
        fma2(acc[3][0], x3, wA.x); fma2(acc[3][1], x3, wA.y);
        fma2(acc[3][2], x3, wB.x); fma2(acc[3][3], x3, wB.y);
    }
    if (HEAD) __syncthreads();   // all reads of xs done before reuse as xh

    float4 b0 = *(const float4*)&b[8 * tx];
    float4 b1 = *(const float4*)&b[8 * tx + 4];
    #pragma unroll
    for (int r = 0; r < 4; r++) {
        int gr = r0 + 4 * ty + r;
        if (gr < N) {
            float* hp = &h[((size_t)gr << 6) + 8 * tx];
            float4 h0 = *(float4*)hp;
            float4 h1 = *(float4*)(hp + 4);
            float2 f0 = unpack2(acc[r][0]), f1 = unpack2(acc[r][1]);
            float2 f2 = unpack2(acc[r][2]), f3 = unpack2(acc[r][3]);
            h0.x += alpha * (f0.x + b0.x); h0.y += alpha * (f0.y + b0.y);
            h0.z += alpha * (f1.x + b0.z); h0.w += alpha * (f1.y + b0.w);
            h1.x += alpha * (f2.x + b1.x); h1.y += alpha * (f2.y + b1.y);
            h1.z += alpha * (f3.x + b1.z); h1.w += alpha * (f3.y + b1.w);
            if (HEAD) {
                float* xh = &xs[(4 * ty + r) * 65 + 8 * tx];
                xh[0] = h0.x; xh[1] = h0.y; xh[2] = h0.z; xh[3] = h0.w;
                xh[4] = h1.x; xh[5] = h1.y; xh[6] = h1.z; xh[7] = h1.w;
            } else {
                *(float4*)hp = h0;
                *(float4*)(hp + 4) = h1;
            }
        }
    }

    if (HEAD) {
        __syncthreads();
        int row = t & 127, th = t >> 7;
        int gr = r0 + row;
        const float* xrow = &xs[row * 65];
        for (int jt = 0; jt < 2; jt++) {
            int jl = (jt * 2 + th) * 8;
            unsigned long long a0 = 0, a1 = 0, a2 = 0, a3 = 0;
            #pragma unroll
            for (int k = 0; k < 64; k++) {
                unsigned long long xv = pack2(xrow[k]);
                const float* wp = &ws2[k * 32 + jl];
                ulonglong2 wA = *(const ulonglong2*)wp;
                ulonglong2 wB = *(const ulonglong2*)(wp + 4);
                fma2(a0, xv, wA.x); fma2(a1, xv, wA.y);
                fma2(a2, xv, wB.x); fma2(a3, xv, wB.y);
            }
            if (gr < N) {
                float2 f0 = unpack2(a0), f1 = unpack2(a1), f2 = unpack2(a2), f3 = unpack2(a3);
                const float* bp = &outb[jl];
                float* op = &out[(size_t)gr * 32 + jl];
                op[0] = f0.x + bp[0]; op[1] = f0.y + bp[1];
                op[2] = f1.x + bp[2]; op[3] = f1.y + bp[3];
                op[4] = f2.x + bp[4]; op[5] = f2.y + bp[5];
                op[6] = f3.x + bp[6]; op[7] = f3.y + bp[7];
            }
        }
    }
}

extern "C" __global__ void __launch_bounds__(256)
k_group_combine(const float* agg, const float* rdeg, const float* W, const float* b,
                const float* alpha_p, float* h, int N) {
    group_combine_impl<0>(agg, rdeg, W, b, alpha_p, h, nullptr, nullptr, nullptr, N);
}
extern "C" __global__ void __launch_bounds__(256)
k_group_combine_head(const float* agg, const float* rdeg, const float* W, const float* b,
                     const float* alpha_p, float* h, const float* outW, const float* outb,
                     float* out, int N) {
    group_combine_impl<1>(agg, rdeg, W, b, alpha_p, h, outW, outb, out, N);
}

// ---------------- launch ----------------
extern "C" void kernel_launch(void* const* d_in, const int* in_sizes, int n_in,
                              void* d_out, int out_size) {
    const float* x      = (const float*)d_in[0];
    const int*   ei     = (const int*)d_in[1];
    const int*   et     = (const int*)d_in[2];
    const float* ew     = (const float*)d_in[3];
    const float* W1     = (const float*)d_in[4];
    const float* W01    = (const float*)d_in[5];
    const float* alpha1 = (const float*)d_in[6];
    const float* projW1 = (const float*)d_in[7];
    const float* projb1 = (const float*)d_in[8];
    const float* W2     = (const float*)d_in[9];
    const float* W02    = (const float*)d_in[10];
    const float* alpha2 = (const float*)d_in[11];
    const float* projW2 = (const float*)d_in[12];
    const float* projb2 = (const float*)d_in[13];
    const float* outW   = (const float*)d_in[14];
    const float* outb   = (const float*)d_in[15];

    int N = in_sizes[0] / 64;
    int E = in_sizes[2];

    float *rdeg, *agg, *xt, *h;
    int *cntflag, *pref, *off, *cursor;
    int2 *erec;
    unsigned *wfrag;
    cudaGetSymbolAddress((void**)&cntflag, g_cntflag);
    cudaGetSymbolAddress((void**)&pref,    g_pref);
    cudaGetSymbolAddress((void**)&off,     g_off);
    cudaGetSymbolAddress((void**)&cursor,  g_cursor);
    cudaGetSymbolAddress((void**)&rdeg,    g_rdeg);
    cudaGetSymbolAddress((void**)&erec,    g_erec);
    cudaGetSymbolAddress((void**)&xt,      g_xt);
    cudaGetSymbolAddress((void**)&h,       g_h);
    cudaGetSymbolAddress((void**)&agg,     g_agg);
    cudaGetSymbolAddress((void**)&wfrag,   g_wfrag);

    static cudaStream_t s2 = nullptr;
    static cudaEvent_t evFork = nullptr, evJoin = nullptr;
    if (s2 == nullptr) {
        cudaStreamCreateWithFlags(&s2, cudaStreamNonBlocking);
        cudaEventCreateWithFlags(&evFork, cudaEventDisableTiming);
        cudaEventCreateWithFlags(&evJoin, cudaEventDisableTiming);
    }

    const int SMEM_M  = (128 * TXP + 2 * 4096) * 4;            // transform: 67584
    const int SMEM_T  = (64 * XS_P + 64 * 64) * 4;             // combine: 50176
    const int SMEM_TH = (64 * XS_P + 64 * 64 + 64 * 32) * 4;   // combine+head: 58368
    cudaFuncSetAttribute(k_transform_mma,      cudaFuncAttributeMaxDynamicSharedMemorySize, SMEM_M);
    cudaFuncSetAttribute(k_group_combine,      cudaFuncAttributeMaxDynamicSharedMemorySize, SMEM_T);
    cudaFuncSetAttribute(k_group_combine_head, cudaFuncAttributeMaxDynamicSharedMemorySize, SMEM_TH);

    int ebl  = (E + 255) / 256;
    int e2bl = (E / 2 + 255) / 256;
    int gthr = (N * 16 + 255) / 256;
    int gbl  = (N + 127) / 128;
    int B1   = (N + 1023) / 1024;

    // ---- fork: CSR build on s2, wprep + transform L1 on main ----
    cudaEventRecord(evFork, 0);
    cudaStreamWaitEvent(s2, evFork, 0);

    k_deg<<<e2bl, 256, 0, s2>>>(ei, cntflag, E);
    k_scanAll<<<B1, 1024, 0, s2>>>(cntflag, cntflag + NMAX, pref,
                                   off, cursor, rdeg, N, E);
    k_fill<<<ebl, 256, 0, s2>>>(ei, et, ew, cursor, erec, cntflag, E);
    cudaEventRecord(evJoin, s2);

    k_wprep<<<160, 256>>>(W01, W1, W02, W2, wfrag);
    k_transform_mma<<<gbl, 256, SMEM_M>>>(x, wfrag, xt, N);

    cudaStreamWaitEvent(0, evJoin, 0);

    // ---- layer 1 ----
    k_rgcn_gather<<<gthr, 256>>>(off, erec, xt, rdeg, h, N);
    k_group_gather<<<gthr, 256>>>(off, erec, h, agg, N);
    k_group_combine<<<gbl, 256, SMEM_T>>>(agg, rdeg, projW1, projb1, alpha1, h, N);

    // ---- layer 2 ----
    k_transform_mma<<<gbl, 256, SMEM_M>>>(h, wfrag + 20480, xt, N);
    k_rgcn_gather<<<gthr, 256>>>(off, erec, xt, rdeg, h, N);
    k_group_gather<<<gthr, 256>>>(off, erec, h, agg, N);
    k_group_combine_head<<<gbl, 256, SMEM_TH>>>(agg, rdeg, projW2, projb2, alpha2, h,
                                                outW, outb, (float*)d_out, N);
}